// round 4
// baseline (speedup 1.0000x reference)
#include <cuda_runtime.h>
#include <math.h>

#define D 128
#define NRBF 20
#define NNODES 25000
#define NEDGES 250000
#define NGRAPHS 512

// ---------------- scratch (device globals; no allocation) ----------------
__device__ float g_state0[NNODES * D];
__device__ float g_state_acc[NNODES * D];
__device__ float g_state_vec[NNODES * 3 * D];
__device__ float g_phi[NNODES * 2 * D];         // per-node phi cols 128..383 (m2|m3)
__device__ float g_UV[NNODES * D];
__device__ float g_Vn[NNODES * D];
__device__ float g_graph[NGRAPHS * D];

typedef unsigned long long u64;

__device__ __forceinline__ float silu_f(float x) {
    return x / (1.0f + __expf(-x));
}

__device__ __forceinline__ u64 pk2(float lo, float hi) {
    u64 r;
    asm("mov.b64 %0, {%1, %2};" : "=l"(r) : "r"(__float_as_uint(lo)), "r"(__float_as_uint(hi)));
    return r;
}
__device__ __forceinline__ float2 upk2(u64 v) {
    unsigned lo, hi;
    asm("mov.b64 {%0, %1}, %2;" : "=r"(lo), "=r"(hi) : "l"(v));
    return make_float2(__uint_as_float(lo), __uint_as_float(hi));
}
__device__ __forceinline__ void fma2(u64& acc, u64 a, u64 b) {
    asm("fma.rn.f32x2 %0, %1, %2, %0;" : "+l"(acc) : "l"(a), "l"(b));
}

// ---------------- init ----------------
__global__ void init_kernel(const float* __restrict__ emb, const int* __restrict__ atype) {
    int stride = gridDim.x * blockDim.x;
    int total = NNODES * 3 * D;
    for (int idx = blockIdx.x * blockDim.x + threadIdx.x; idx < total; idx += stride) {
        g_state_vec[idx] = 0.0f;
        if (idx < NNODES * D) {
            int n = idx >> 7;
            int j = idx & 127;
            g_state0[idx] = emb[atype[n] * D + j];
            g_state_acc[idx] = 0.0f;
        }
        if (idx < NGRAPHS * D) g_graph[idx] = 0.0f;
    }
}

// ---------------- per-node phi MLP ----------------
__global__ __launch_bounds__(128) void node_phi_kernel(
    const float* __restrict__ phi_W1, const float* __restrict__ phi_b1,
    const float* __restrict__ phi_W2, const float* __restrict__ phi_b2)
{
    __shared__ float sA[64][132];
    __shared__ float sW[32][132];
    const int t = threadIdx.x;
    const int n0 = blockIdx.x * 64;

    for (int k = t; k < 64 * 32; k += 128) {
        int row = k >> 5, c4 = k & 31;
        int n = n0 + row;
        float4 v = make_float4(0.f, 0.f, 0.f, 0.f);
        if (n < NNODES) v = ((const float4*)(g_state0 + (size_t)n * D))[c4];
        *(float4*)(&sA[row][c4 * 4]) = v;
    }

    const int ty = t >> 4;
    const int tx = t & 15;
    const int r0 = ty * 8, c0 = tx * 8;

    u64 acc[8][4];
    #pragma unroll
    for (int i = 0; i < 8; i++)
        #pragma unroll
        for (int j = 0; j < 4; j++) acc[i][j] = 0ull;

    for (int k0 = 0; k0 < D; k0 += 32) {
        __syncthreads();
        for (int k = t; k < 32 * 32; k += 128) {
            int row = k >> 5, c4 = k & 31;
            *(float4*)(&sW[row][c4 * 4]) = __ldg((const float4*)(phi_W1 + (k0 + row) * D + c4 * 4));
        }
        __syncthreads();
        for (int kk = 0; kk < 32; kk++) {
            u64 ad[8];
            #pragma unroll
            for (int i = 0; i < 8; i++) {
                float a = sA[r0 + i][k0 + kk];
                ad[i] = pk2(a, a);
            }
            float4 b0 = *(const float4*)(&sW[kk][c0]);
            float4 b1 = *(const float4*)(&sW[kk][c0 + 4]);
            u64 bp[4] = {pk2(b0.x, b0.y), pk2(b0.z, b0.w), pk2(b1.x, b1.y), pk2(b1.z, b1.w)};
            #pragma unroll
            for (int i = 0; i < 8; i++)
                #pragma unroll
                for (int j = 0; j < 4; j++) fma2(acc[i][j], ad[i], bp[j]);
        }
    }
    __syncthreads();
    #pragma unroll
    for (int j = 0; j < 4; j++) {
        float bias0 = __ldg(&phi_b1[c0 + 2 * j]);
        float bias1 = __ldg(&phi_b1[c0 + 2 * j + 1]);
        #pragma unroll
        for (int i = 0; i < 8; i++) {
            float2 v = upk2(acc[i][j]);
            sA[r0 + i][c0 + 2 * j] = silu_f(v.x + bias0);
            sA[r0 + i][c0 + 2 * j + 1] = silu_f(v.y + bias1);
        }
    }
    __syncthreads();

    #pragma unroll 1
    for (int half = 0; half < 2; half++) {
        const int cb = D + half * D;
        u64 acc2[8][4];
        #pragma unroll
        for (int i = 0; i < 8; i++)
            #pragma unroll
            for (int j = 0; j < 4; j++) acc2[i][j] = 0ull;

        for (int k0 = 0; k0 < D; k0 += 32) {
            __syncthreads();
            for (int k = t; k < 32 * 32; k += 128) {
                int row = k >> 5, c4 = k & 31;
                *(float4*)(&sW[row][c4 * 4]) = __ldg((const float4*)(phi_W2 + (k0 + row) * 384 + cb + c4 * 4));
            }
            __syncthreads();
            for (int kk = 0; kk < 32; kk++) {
                u64 ad[8];
                #pragma unroll
                for (int i = 0; i < 8; i++) {
                    float a = sA[r0 + i][k0 + kk];
                    ad[i] = pk2(a, a);
                }
                float4 b0 = *(const float4*)(&sW[kk][c0]);
                float4 b1 = *(const float4*)(&sW[kk][c0 + 4]);
                u64 bp[4] = {pk2(b0.x, b0.y), pk2(b0.z, b0.w), pk2(b1.x, b1.y), pk2(b1.z, b1.w)};
                #pragma unroll
                for (int i = 0; i < 8; i++)
                    #pragma unroll
                    for (int j = 0; j < 4; j++) fma2(acc2[i][j], ad[i], bp[j]);
            }
        }

        #pragma unroll
        for (int i = 0; i < 8; i++) {
            int n = n0 + r0 + i;
            if (n < NNODES) {
                float2 p0 = upk2(acc2[i][0]);
                float2 p1 = upk2(acc2[i][1]);
                float2 p2 = upk2(acc2[i][2]);
                float2 p3 = upk2(acc2[i][3]);
                float4* dst = (float4*)(g_phi + (size_t)n * 256 + half * D + c0);
                dst[0] = make_float4(p0.x + __ldg(&phi_b2[cb + c0 + 0]),
                                     p0.y + __ldg(&phi_b2[cb + c0 + 1]),
                                     p1.x + __ldg(&phi_b2[cb + c0 + 2]),
                                     p1.y + __ldg(&phi_b2[cb + c0 + 3]));
                dst[1] = make_float4(p2.x + __ldg(&phi_b2[cb + c0 + 4]),
                                     p2.y + __ldg(&phi_b2[cb + c0 + 5]),
                                     p3.x + __ldg(&phi_b2[cb + c0 + 6]),
                                     p3.y + __ldg(&phi_b2[cb + c0 + 7]));
            }
        }
    }
}

// ---------------- edge kernel: RBF filter + gather phi[from] + scatter ----------------
__global__ __launch_bounds__(256) void edge_kernel(
    const float* __restrict__ edge_vec,
    const float* __restrict__ filt_W, const float* __restrict__ filt_b,
    const int* __restrict__ node_from, const int* __restrict__ node_to)
{
    __shared__ float sRbf[8][20];
    __shared__ float sFc[8];
    __shared__ float sDist[8];
    __shared__ float sNorm[8][3];
    __shared__ int   sFrom[8];
    __shared__ int   sTo[8];

    const int t = threadIdx.x;
    const int e0 = blockIdx.x * 8;
    const float PI = 3.14159265358979323846f;

    if (t < 8) {
        int e = e0 + t;
        float x = edge_vec[3 * e + 0];
        float y = edge_vec[3 * e + 1];
        float z = edge_vec[3 * e + 2];
        float d = sqrtf(x * x + y * y + z * z);
        float inv = 1.0f / d;
        float fcv = (d < 10.0f) ? 0.5f * (cosf(PI * d * 0.1f) + 1.0f) : 0.0f;
        sDist[t] = d;
        sFc[t] = fcv * inv;
        sNorm[t][0] = x * inv; sNorm[t][1] = y * inv; sNorm[t][2] = z * inv;
        sFrom[t] = node_from[e];
        sTo[t] = node_to[e];
    }
    __syncthreads();
    if (t < 160) {
        int le = t / 20, r = t % 20;
        sRbf[le][r] = sinf((float)(r + 1) * PI * sDist[le] * 0.1f) * sFc[le];
    }
    __syncthreads();

    const int le = t >> 5;
    const int j0 = (t & 31) << 3;
    const float fc = sFc[le] * sDist[le];

    float w[8];
    #pragma unroll
    for (int j = 0; j < 8; j++) w[j] = fc * __ldg(&filt_b[128 + j0 + j]);
    #pragma unroll
    for (int r = 0; r < NRBF; r++) {
        float a = sRbf[le][r];
        float4 b0 = __ldg((const float4*)(filt_W + r * 384 + 128 + j0));
        float4 b1 = __ldg((const float4*)(filt_W + r * 384 + 128 + j0 + 4));
        w[0] += a * b0.x; w[1] += a * b0.y; w[2] += a * b0.z; w[3] += a * b0.w;
        w[4] += a * b1.x; w[5] += a * b1.y; w[6] += a * b1.z; w[7] += a * b1.w;
    }

    const float4* ph = (const float4*)(g_phi + (size_t)sFrom[le] * 256 + j0);
    float4 p0 = ph[0];
    float4 p1 = ph[1];
    float pf[8];
    pf[0] = p0.x * w[0]; pf[1] = p0.y * w[1]; pf[2] = p0.z * w[2]; pf[3] = p0.w * w[3];
    pf[4] = p1.x * w[4]; pf[5] = p1.y * w[5]; pf[6] = p1.z * w[6]; pf[7] = p1.w * w[7];

    const int to = sTo[le];
    if (j0 < 128) {
        float4* dst = (float4*)(g_state_acc + (size_t)to * D + j0);
        atomicAdd(dst,     make_float4(pf[0], pf[1], pf[2], pf[3]));
        atomicAdd(dst + 1, make_float4(pf[4], pf[5], pf[6], pf[7]));
    } else {
        const int jj = j0 - 128;
        float n0 = sNorm[le][0], n1 = sNorm[le][1], n2 = sNorm[le][2];
        float* base = g_state_vec + (size_t)to * (3 * D) + jj;
        atomicAdd((float4*)(base),             make_float4(n0 * pf[0], n0 * pf[1], n0 * pf[2], n0 * pf[3]));
        atomicAdd((float4*)(base + 4),         make_float4(n0 * pf[4], n0 * pf[5], n0 * pf[6], n0 * pf[7]));
        atomicAdd((float4*)(base + D),         make_float4(n1 * pf[0], n1 * pf[1], n1 * pf[2], n1 * pf[3]));
        atomicAdd((float4*)(base + D + 4),     make_float4(n1 * pf[4], n1 * pf[5], n1 * pf[6], n1 * pf[7]));
        atomicAdd((float4*)(base + 2 * D),     make_float4(n2 * pf[0], n2 * pf[1], n2 * pf[2], n2 * pf[3]));
        atomicAdd((float4*)(base + 2 * D + 4), make_float4(n2 * pf[4], n2 * pf[5], n2 * pf[6], n2 * pf[7]));
    }
}

// ---------------- fused UV kernel: Up/Vp GEMM + UV/Vn reduce ----------------
// 16 nodes / block, 256 threads. A tile stored TRANSPOSED in smem as
// sAt[k][node*4+comp] so a thread grabs its node's 3 components in ONE LDS.128.
__global__ __launch_bounds__(256) void uv_kernel(
    const float* __restrict__ U_W, const float* __restrict__ V_W)
{
    __shared__ float sAt[128][64];   // [k][nl*4+comp] (comp 3 = pad)
    __shared__ float sU[32][132];
    __shared__ float sV[32][132];
    const int t = threadIdx.x;
    const int nb0 = blockIdx.x * 16;
    const int rb = nb0 * 3;
    const int NR = NNODES * 3;

    // load + transpose: 48 rows x 128 cols
    for (int k = t; k < 48 * 32; k += 256) {
        int row = k >> 5, c4 = k & 31;
        int r = rb + row;
        float4 v = make_float4(0.f, 0.f, 0.f, 0.f);
        if (r < NR) v = ((const float4*)(g_state_vec + (size_t)r * D))[c4];
        int nl = row / 3, comp = row - nl * 3;
        int col = nl * 4 + comp;
        sAt[c4 * 4 + 0][col] = v.x;
        sAt[c4 * 4 + 1][col] = v.y;
        sAt[c4 * 4 + 2][col] = v.z;
        sAt[c4 * 4 + 3][col] = v.w;
    }

    const int nl = t >> 4;          // node within block
    const int c0 = (t & 15) * 8;    // column group

    u64 au[3][4], av[3][4];
    #pragma unroll
    for (int c = 0; c < 3; c++)
        #pragma unroll
        for (int j = 0; j < 4; j++) { au[c][j] = 0ull; av[c][j] = 0ull; }

    for (int k0 = 0; k0 < D; k0 += 32) {
        __syncthreads();
        for (int k = t; k < 32 * 32; k += 256) {
            int row = k >> 5, c4 = k & 31;
            *(float4*)(&sU[row][c4 * 4]) = __ldg((const float4*)(U_W + (k0 + row) * D + c4 * 4));
            *(float4*)(&sV[row][c4 * 4]) = __ldg((const float4*)(V_W + (k0 + row) * D + c4 * 4));
        }
        __syncthreads();
        #pragma unroll 4
        for (int kk = 0; kk < 32; kk++) {
            float4 a = *(const float4*)(&sAt[k0 + kk][nl * 4]);
            u64 d0 = pk2(a.x, a.x), d1 = pk2(a.y, a.y), d2 = pk2(a.z, a.z);
            float4 u0 = *(const float4*)(&sU[kk][c0]);
            float4 u1 = *(const float4*)(&sU[kk][c0 + 4]);
            float4 v0 = *(const float4*)(&sV[kk][c0]);
            float4 v1 = *(const float4*)(&sV[kk][c0 + 4]);
            u64 bu[4] = {pk2(u0.x, u0.y), pk2(u0.z, u0.w), pk2(u1.x, u1.y), pk2(u1.z, u1.w)};
            u64 bv[4] = {pk2(v0.x, v0.y), pk2(v0.z, v0.w), pk2(v1.x, v1.y), pk2(v1.z, v1.w)};
            #pragma unroll
            for (int j = 0; j < 4; j++) {
                fma2(au[0][j], d0, bu[j]);
                fma2(au[1][j], d1, bu[j]);
                fma2(au[2][j], d2, bu[j]);
                fma2(av[0][j], d0, bv[j]);
                fma2(av[1][j], d1, bv[j]);
                fma2(av[2][j], d2, bv[j]);
            }
        }
    }

    int node = nb0 + nl;
    if (node < NNODES) {
        float uvv[8], vnv[8];
        #pragma unroll
        for (int j = 0; j < 4; j++) {
            float2 A0 = upk2(au[0][j]), A1 = upk2(au[1][j]), A2 = upk2(au[2][j]);
            float2 B0 = upk2(av[0][j]), B1 = upk2(av[1][j]), B2 = upk2(av[2][j]);
            uvv[2 * j]     = A0.x * B0.x + A1.x * B1.x + A2.x * B2.x;
            uvv[2 * j + 1] = A0.y * B0.y + A1.y * B1.y + A2.y * B2.y;
            vnv[2 * j]     = sqrtf(B0.x * B0.x + B1.x * B1.x + B2.x * B2.x);
            vnv[2 * j + 1] = sqrtf(B0.y * B0.y + B1.y * B1.y + B2.y * B2.y);
        }
        float4* du = (float4*)(g_UV + (size_t)node * D + c0);
        float4* dv = (float4*)(g_Vn + (size_t)node * D + c0);
        du[0] = make_float4(uvv[0], uvv[1], uvv[2], uvv[3]);
        du[1] = make_float4(uvv[4], uvv[5], uvv[6], uvv[7]);
        dv[0] = make_float4(vnv[0], vnv[1], vnv[2], vnv[3]);
        dv[1] = make_float4(vnv[4], vnv[5], vnv[6], vnv[7]);
    }
}

// ---------------- node update MLP + segment-sum ----------------
__global__ __launch_bounds__(128) void update_kernel(
    const float* __restrict__ upd_W1, const float* __restrict__ upd_b1,
    const float* __restrict__ upd_W2, const float* __restrict__ upd_b2,
    const int* __restrict__ node_graph_index)
{
    __shared__ float sA[32][260];
    __shared__ float sW[32][264];
    const int t = threadIdx.x;
    const int n0 = blockIdx.x * 32;

    for (int k = t; k < 32 * 64; k += 128) {
        int row = k >> 6, c4 = k & 63;
        int n = n0 + row;
        float4 v = make_float4(0.f, 0.f, 0.f, 0.f);
        if (n < NNODES) {
            if (c4 < 32) {
                v = ((const float4*)(g_Vn + (size_t)n * D))[c4];
            } else {
                float4 s0 = ((const float4*)(g_state0 + (size_t)n * D))[c4 - 32];
                float4 s1 = ((const float4*)(g_state_acc + (size_t)n * D))[c4 - 32];
                v = make_float4(s0.x + s1.x, s0.y + s1.y, s0.z + s1.z, s0.w + s1.w);
            }
        }
        *(float4*)(&sA[row][c4 * 4]) = v;
    }

    const int ty = t >> 4;
    const int tx = t & 15;
    const int r0 = ty * 4, c0 = tx * 8;

    u64 acc[4][4];
    #pragma unroll
    for (int i = 0; i < 4; i++)
        #pragma unroll
        for (int j = 0; j < 4; j++) acc[i][j] = 0ull;

    for (int k0 = 0; k0 < 2 * D; k0 += 32) {
        __syncthreads();
        for (int k = t; k < 32 * 32; k += 128) {
            int row = k >> 5, c4 = k & 31;
            *(float4*)(&sW[row][c4 * 4]) = __ldg((const float4*)(upd_W1 + (k0 + row) * D + c4 * 4));
        }
        __syncthreads();
        for (int kk = 0; kk < 32; kk++) {
            u64 ad[4];
            #pragma unroll
            for (int i = 0; i < 4; i++) {
                float a = sA[r0 + i][k0 + kk];
                ad[i] = pk2(a, a);
            }
            float4 b0 = *(const float4*)(&sW[kk][c0]);
            float4 b1 = *(const float4*)(&sW[kk][c0 + 4]);
            u64 bp[4] = {pk2(b0.x, b0.y), pk2(b0.z, b0.w), pk2(b1.x, b1.y), pk2(b1.z, b1.w)};
            #pragma unroll
            for (int i = 0; i < 4; i++)
                #pragma unroll
                for (int j = 0; j < 4; j++) fma2(acc[i][j], ad[i], bp[j]);
        }
    }
    __syncthreads();
    #pragma unroll
    for (int j = 0; j < 4; j++) {
        float bias0 = __ldg(&upd_b1[c0 + 2 * j]);
        float bias1 = __ldg(&upd_b1[c0 + 2 * j + 1]);
        #pragma unroll
        for (int i = 0; i < 4; i++) {
            float2 v = upk2(acc[i][j]);
            sA[r0 + i][c0 + 2 * j] = silu_f(v.x + bias0);
            sA[r0 + i][c0 + 2 * j + 1] = silu_f(v.y + bias1);
        }
    }
    __syncthreads();

    u64 asv[4][4], ass[4][4];
    #pragma unroll
    for (int i = 0; i < 4; i++)
        #pragma unroll
        for (int j = 0; j < 4; j++) { asv[i][j] = 0ull; ass[i][j] = 0ull; }

    for (int k0 = 0; k0 < D; k0 += 32) {
        __syncthreads();
        for (int k = t; k < 32 * 64; k += 128) {
            int row = k >> 6, c4 = k & 63;
            *(float4*)(&sW[row][c4 * 4]) = __ldg((const float4*)(upd_W2 + (k0 + row) * 384 + 128 + c4 * 4));
        }
        __syncthreads();
        for (int kk = 0; kk < 32; kk++) {
            u64 ad[4];
            #pragma unroll
            for (int i = 0; i < 4; i++) {
                float a = sA[r0 + i][k0 + kk];
                ad[i] = pk2(a, a);
            }
            float4 b0 = *(const float4*)(&sW[kk][c0]);
            float4 b1 = *(const float4*)(&sW[kk][c0 + 4]);
            float4 b2 = *(const float4*)(&sW[kk][128 + c0]);
            float4 b3 = *(const float4*)(&sW[kk][128 + c0 + 4]);
            u64 bsv[4] = {pk2(b0.x, b0.y), pk2(b0.z, b0.w), pk2(b1.x, b1.y), pk2(b1.z, b1.w)};
            u64 bss[4] = {pk2(b2.x, b2.y), pk2(b2.z, b2.w), pk2(b3.x, b3.y), pk2(b3.z, b3.w)};
            #pragma unroll
            for (int i = 0; i < 4; i++)
                #pragma unroll
                for (int j = 0; j < 4; j++) {
                    fma2(asv[i][j], ad[i], bsv[j]);
                    fma2(ass[i][j], ad[i], bss[j]);
                }
        }
    }

    int base = __ldg(&node_graph_index[0]);
    #pragma unroll
    for (int i = 0; i < 4; i++) {
        int n = n0 + r0 + i;
        if (n < NNODES) {
            int g = __ldg(&node_graph_index[n]) - base;
            float* dst = g_graph + (size_t)g * D + c0;
            float vals[8];
            #pragma unroll
            for (int j = 0; j < 4; j++) {
                float2 sv = upk2(asv[i][j]);
                float2 ss = upk2(ass[i][j]);
                float uv0 = g_UV[(size_t)n * D + c0 + 2 * j];
                float uv1 = g_UV[(size_t)n * D + c0 + 2 * j + 1];
                float a_sv0 = sv.x + __ldg(&upd_b2[D + c0 + 2 * j]);
                float a_sv1 = sv.y + __ldg(&upd_b2[D + c0 + 2 * j + 1]);
                float a_ss0 = ss.x + __ldg(&upd_b2[2 * D + c0 + 2 * j]);
                float a_ss1 = ss.y + __ldg(&upd_b2[2 * D + c0 + 2 * j + 1]);
                vals[2 * j]     = sA[r0 + i][D + c0 + 2 * j]     + uv0 * a_sv0 + a_ss0;
                vals[2 * j + 1] = sA[r0 + i][D + c0 + 2 * j + 1] + uv1 * a_sv1 + a_ss1;
            }
            atomicAdd((float4*)dst,       make_float4(vals[0], vals[1], vals[2], vals[3]));
            atomicAdd((float4*)(dst + 4), make_float4(vals[4], vals[5], vals[6], vals[7]));
        }
    }
}

// ---------------- output MLP: 512 graphs ----------------
__global__ void out_kernel(
    const float* __restrict__ out_W1, const float* __restrict__ out_b1,
    const float* __restrict__ out_W2, const float* __restrict__ out_b2,
    float* __restrict__ out)
{
    __shared__ float sG[D];
    __shared__ float sRed[D];
    const int g = blockIdx.x;
    const int t = threadIdx.x;
    sG[t] = g_graph[(size_t)g * D + t];
    __syncthreads();
    float x = 0.f;
    #pragma unroll 8
    for (int k = 0; k < D; k++) x += sG[k] * __ldg(&out_W1[k * D + t]);
    x += __ldg(&out_b1[t]);
    float p = silu_f(x) * __ldg(&out_W2[t]);
    sRed[t] = p;
    __syncthreads();
    for (int s = 64; s > 0; s >>= 1) {
        if (t < s) sRed[t] += sRed[t + s];
        __syncthreads();
    }
    if (t == 0) out[g] = sRed[0] + __ldg(&out_b2[0]);
}

// ---------------- launch ----------------
extern "C" void kernel_launch(void* const* d_in, const int* in_sizes, int n_in,
                              void* d_out, int out_size)
{
    const float* edge_vec  = (const float*)d_in[0];
    const float* embedding = (const float*)d_in[1];
    const float* phi_W1 = (const float*)d_in[2];
    const float* phi_b1 = (const float*)d_in[3];
    const float* phi_W2 = (const float*)d_in[4];
    const float* phi_b2 = (const float*)d_in[5];
    const float* filt_W = (const float*)d_in[6];
    const float* filt_b = (const float*)d_in[7];
    const float* upd_W1 = (const float*)d_in[8];
    const float* upd_b1 = (const float*)d_in[9];
    const float* upd_W2 = (const float*)d_in[10];
    const float* upd_b2 = (const float*)d_in[11];
    const float* out_W1 = (const float*)d_in[12];
    const float* out_b1 = (const float*)d_in[13];
    const float* out_W2 = (const float*)d_in[14];
    const float* out_b2 = (const float*)d_in[15];
    const float* U_W    = (const float*)d_in[16];
    const float* V_W    = (const float*)d_in[17];
    const int* atom_types = (const int*)d_in[18];
    const int* node_from  = (const int*)d_in[19];
    const int* node_to    = (const int*)d_in[20];
    const int* node_graph_index = (const int*)d_in[21];
    float* out = (float*)d_out;

    init_kernel<<<2048, 256>>>(embedding, atom_types);
    node_phi_kernel<<<(NNODES + 63) / 64, 128>>>(phi_W1, phi_b1, phi_W2, phi_b2);
    edge_kernel<<<NEDGES / 8, 256>>>(edge_vec, filt_W, filt_b, node_from, node_to);
    uv_kernel<<<(NNODES + 15) / 16, 256>>>(U_W, V_W);
    update_kernel<<<(NNODES + 31) / 32, 128>>>(upd_W1, upd_b1, upd_W2, upd_b2, node_graph_index);
    out_kernel<<<NGRAPHS, D>>>(out_W1, out_b1, out_W2, out_b2, out);
}

// round 5
// speedup vs baseline: 1.0142x; 1.0142x over previous
#include <cuda_runtime.h>
#include <math.h>

#define D 128
#define NRBF 20
#define NNODES 25000
#define NEDGES 250000
#define NGRAPHS 512

// ---------------- scratch (device globals; no allocation) ----------------
__device__ float g_state0[NNODES * D];
__device__ float g_state_acc[NNODES * D];
__device__ float g_state_vec[NNODES * 3 * D];
__device__ float g_phi[NNODES * 2 * D];         // per-node phi cols 128..383 (m2|m3)
__device__ float g_UV[NNODES * D];
__device__ float g_Vn[NNODES * D];
__device__ float g_graph[NGRAPHS * D];

typedef unsigned long long u64;

__device__ __forceinline__ float silu_f(float x) {
    return x / (1.0f + __expf(-x));
}

__device__ __forceinline__ u64 pk2(float lo, float hi) {
    u64 r;
    asm("mov.b64 %0, {%1, %2};" : "=l"(r) : "r"(__float_as_uint(lo)), "r"(__float_as_uint(hi)));
    return r;
}
__device__ __forceinline__ float2 upk2(u64 v) {
    unsigned lo, hi;
    asm("mov.b64 {%0, %1}, %2;" : "=r"(lo), "=r"(hi) : "l"(v));
    return make_float2(__uint_as_float(lo), __uint_as_float(hi));
}
__device__ __forceinline__ void fma2(u64& acc, u64 a, u64 b) {
    asm("fma.rn.f32x2 %0, %1, %2, %0;" : "+l"(acc) : "l"(a), "l"(b));
}

// ---------------- init ----------------
__global__ void init_kernel(const float* __restrict__ emb, const int* __restrict__ atype) {
    int stride = gridDim.x * blockDim.x;
    int total = NNODES * 3 * D;
    for (int idx = blockIdx.x * blockDim.x + threadIdx.x; idx < total; idx += stride) {
        g_state_vec[idx] = 0.0f;
        if (idx < NNODES * D) {
            int n = idx >> 7;
            int j = idx & 127;
            g_state0[idx] = emb[atype[n] * D + j];
            g_state_acc[idx] = 0.0f;
        }
        if (idx < NGRAPHS * D) g_graph[idx] = 0.0f;
    }
}

// ---------------- per-node phi MLP ----------------
__global__ __launch_bounds__(128) void node_phi_kernel(
    const float* __restrict__ phi_W1, const float* __restrict__ phi_b1,
    const float* __restrict__ phi_W2, const float* __restrict__ phi_b2)
{
    __shared__ float sA[64][132];
    __shared__ float sW[32][132];
    const int t = threadIdx.x;
    const int n0 = blockIdx.x * 64;

    for (int k = t; k < 64 * 32; k += 128) {
        int row = k >> 5, c4 = k & 31;
        int n = n0 + row;
        float4 v = make_float4(0.f, 0.f, 0.f, 0.f);
        if (n < NNODES) v = ((const float4*)(g_state0 + (size_t)n * D))[c4];
        *(float4*)(&sA[row][c4 * 4]) = v;
    }

    const int ty = t >> 4;
    const int tx = t & 15;
    const int r0 = ty * 8, c0 = tx * 8;

    u64 acc[8][4];
    #pragma unroll
    for (int i = 0; i < 8; i++)
        #pragma unroll
        for (int j = 0; j < 4; j++) acc[i][j] = 0ull;

    for (int k0 = 0; k0 < D; k0 += 32) {
        __syncthreads();
        for (int k = t; k < 32 * 32; k += 128) {
            int row = k >> 5, c4 = k & 31;
            *(float4*)(&sW[row][c4 * 4]) = __ldg((const float4*)(phi_W1 + (k0 + row) * D + c4 * 4));
        }
        __syncthreads();
        for (int kk = 0; kk < 32; kk++) {
            u64 ad[8];
            #pragma unroll
            for (int i = 0; i < 8; i++) {
                float a = sA[r0 + i][k0 + kk];
                ad[i] = pk2(a, a);
            }
            ulonglong2 q0 = *(const ulonglong2*)(&sW[kk][c0]);
            ulonglong2 q1 = *(const ulonglong2*)(&sW[kk][c0 + 4]);
            u64 bp[4] = {q0.x, q0.y, q1.x, q1.y};
            #pragma unroll
            for (int i = 0; i < 8; i++)
                #pragma unroll
                for (int j = 0; j < 4; j++) fma2(acc[i][j], ad[i], bp[j]);
        }
    }
    __syncthreads();
    #pragma unroll
    for (int j = 0; j < 4; j++) {
        float bias0 = __ldg(&phi_b1[c0 + 2 * j]);
        float bias1 = __ldg(&phi_b1[c0 + 2 * j + 1]);
        #pragma unroll
        for (int i = 0; i < 8; i++) {
            float2 v = upk2(acc[i][j]);
            sA[r0 + i][c0 + 2 * j] = silu_f(v.x + bias0);
            sA[r0 + i][c0 + 2 * j + 1] = silu_f(v.y + bias1);
        }
    }
    __syncthreads();

    #pragma unroll 1
    for (int half = 0; half < 2; half++) {
        const int cb = D + half * D;
        u64 acc2[8][4];
        #pragma unroll
        for (int i = 0; i < 8; i++)
            #pragma unroll
            for (int j = 0; j < 4; j++) acc2[i][j] = 0ull;

        for (int k0 = 0; k0 < D; k0 += 32) {
            __syncthreads();
            for (int k = t; k < 32 * 32; k += 128) {
                int row = k >> 5, c4 = k & 31;
                *(float4*)(&sW[row][c4 * 4]) = __ldg((const float4*)(phi_W2 + (k0 + row) * 384 + cb + c4 * 4));
            }
            __syncthreads();
            for (int kk = 0; kk < 32; kk++) {
                u64 ad[8];
                #pragma unroll
                for (int i = 0; i < 8; i++) {
                    float a = sA[r0 + i][k0 + kk];
                    ad[i] = pk2(a, a);
                }
                ulonglong2 q0 = *(const ulonglong2*)(&sW[kk][c0]);
                ulonglong2 q1 = *(const ulonglong2*)(&sW[kk][c0 + 4]);
                u64 bp[4] = {q0.x, q0.y, q1.x, q1.y};
                #pragma unroll
                for (int i = 0; i < 8; i++)
                    #pragma unroll
                    for (int j = 0; j < 4; j++) fma2(acc2[i][j], ad[i], bp[j]);
            }
        }

        #pragma unroll
        for (int i = 0; i < 8; i++) {
            int n = n0 + r0 + i;
            if (n < NNODES) {
                float2 p0 = upk2(acc2[i][0]);
                float2 p1 = upk2(acc2[i][1]);
                float2 p2 = upk2(acc2[i][2]);
                float2 p3 = upk2(acc2[i][3]);
                float4* dst = (float4*)(g_phi + (size_t)n * 256 + half * D + c0);
                dst[0] = make_float4(p0.x + __ldg(&phi_b2[cb + c0 + 0]),
                                     p0.y + __ldg(&phi_b2[cb + c0 + 1]),
                                     p1.x + __ldg(&phi_b2[cb + c0 + 2]),
                                     p1.y + __ldg(&phi_b2[cb + c0 + 3]));
                dst[1] = make_float4(p2.x + __ldg(&phi_b2[cb + c0 + 4]),
                                     p2.y + __ldg(&phi_b2[cb + c0 + 5]),
                                     p3.x + __ldg(&phi_b2[cb + c0 + 6]),
                                     p3.y + __ldg(&phi_b2[cb + c0 + 7]));
            }
        }
    }
}

// ---------------- edge kernel: RBF filter + gather phi[from] + scatter ----------------
__global__ __launch_bounds__(256) void edge_kernel(
    const float* __restrict__ edge_vec,
    const float* __restrict__ filt_W, const float* __restrict__ filt_b,
    const int* __restrict__ node_from, const int* __restrict__ node_to)
{
    __shared__ float sRbf[8][20];
    __shared__ float sFc[8];
    __shared__ float sDist[8];
    __shared__ float sNorm[8][3];
    __shared__ int   sFrom[8];
    __shared__ int   sTo[8];

    const int t = threadIdx.x;
    const int e0 = blockIdx.x * 8;
    const float PI = 3.14159265358979323846f;

    if (t < 8) {
        int e = e0 + t;
        float x = edge_vec[3 * e + 0];
        float y = edge_vec[3 * e + 1];
        float z = edge_vec[3 * e + 2];
        float d = sqrtf(x * x + y * y + z * z);
        float inv = 1.0f / d;
        float fcv = (d < 10.0f) ? 0.5f * (cosf(PI * d * 0.1f) + 1.0f) : 0.0f;
        sDist[t] = d;
        sFc[t] = fcv * inv;
        sNorm[t][0] = x * inv; sNorm[t][1] = y * inv; sNorm[t][2] = z * inv;
        sFrom[t] = node_from[e];
        sTo[t] = node_to[e];
    }
    __syncthreads();
    if (t < 160) {
        int le = t / 20, r = t % 20;
        sRbf[le][r] = sinf((float)(r + 1) * PI * sDist[le] * 0.1f) * sFc[le];
    }
    __syncthreads();

    const int le = t >> 5;
    const int j0 = (t & 31) << 3;
    const float fc = sFc[le] * sDist[le];

    float w[8];
    #pragma unroll
    for (int j = 0; j < 8; j++) w[j] = fc * __ldg(&filt_b[128 + j0 + j]);
    #pragma unroll
    for (int r = 0; r < NRBF; r++) {
        float a = sRbf[le][r];
        float4 b0 = __ldg((const float4*)(filt_W + r * 384 + 128 + j0));
        float4 b1 = __ldg((const float4*)(filt_W + r * 384 + 128 + j0 + 4));
        w[0] += a * b0.x; w[1] += a * b0.y; w[2] += a * b0.z; w[3] += a * b0.w;
        w[4] += a * b1.x; w[5] += a * b1.y; w[6] += a * b1.z; w[7] += a * b1.w;
    }

    const float4* ph = (const float4*)(g_phi + (size_t)sFrom[le] * 256 + j0);
    float4 p0 = ph[0];
    float4 p1 = ph[1];
    float pf[8];
    pf[0] = p0.x * w[0]; pf[1] = p0.y * w[1]; pf[2] = p0.z * w[2]; pf[3] = p0.w * w[3];
    pf[4] = p1.x * w[4]; pf[5] = p1.y * w[5]; pf[6] = p1.z * w[6]; pf[7] = p1.w * w[7];

    const int to = sTo[le];
    if (j0 < 128) {
        float4* dst = (float4*)(g_state_acc + (size_t)to * D + j0);
        atomicAdd(dst,     make_float4(pf[0], pf[1], pf[2], pf[3]));
        atomicAdd(dst + 1, make_float4(pf[4], pf[5], pf[6], pf[7]));
    } else {
        const int jj = j0 - 128;
        float n0 = sNorm[le][0], n1 = sNorm[le][1], n2 = sNorm[le][2];
        float* base = g_state_vec + (size_t)to * (3 * D) + jj;
        atomicAdd((float4*)(base),             make_float4(n0 * pf[0], n0 * pf[1], n0 * pf[2], n0 * pf[3]));
        atomicAdd((float4*)(base + 4),         make_float4(n0 * pf[4], n0 * pf[5], n0 * pf[6], n0 * pf[7]));
        atomicAdd((float4*)(base + D),         make_float4(n1 * pf[0], n1 * pf[1], n1 * pf[2], n1 * pf[3]));
        atomicAdd((float4*)(base + D + 4),     make_float4(n1 * pf[4], n1 * pf[5], n1 * pf[6], n1 * pf[7]));
        atomicAdd((float4*)(base + 2 * D),     make_float4(n2 * pf[0], n2 * pf[1], n2 * pf[2], n2 * pf[3]));
        atomicAdd((float4*)(base + 2 * D + 4), make_float4(n2 * pf[4], n2 * pf[5], n2 * pf[6], n2 * pf[7]));
    }
}

// ---------------- fused UV kernel: Up/Vp GEMM + UV/Vn reduce ----------------
// 16 nodes / block, 256 threads. A transposed in smem with pad-68 rows:
// conflict-light scalar fill, aligned LDS.128 broadcast fetch in compute.
// U/V staged in 16-row k-tiles; B pairs loaded directly as u64 (no packing movs).
__global__ __launch_bounds__(256) void uv_kernel(
    const float* __restrict__ U_W, const float* __restrict__ V_W)
{
    __shared__ float sAt[128][68];   // [k][nl*4+comp], pad col 3; 34.8KB
    __shared__ float sU[16][132];    // 8.4KB
    __shared__ float sV[16][132];    // 8.4KB
    const int t = threadIdx.x;
    const int nb0 = blockIdx.x * 16;
    const int rb = nb0 * 3;
    const int NR = NNODES * 3;

    // element-wise transpose fill: rows=node-comp, cols=k.
    // consecutive threads -> consecutive k: LDG coalesced, STS 4-way conflict max.
    for (int idx = t; idx < 48 * 128; idx += 256) {
        int row = idx >> 7;           // 0..47
        int k = idx & 127;
        int r = rb + row;
        float v = (r < NR) ? g_state_vec[(size_t)r * D + k] : 0.f;
        int nl = row / 3, comp = row - nl * 3;
        sAt[k][nl * 4 + comp] = v;
    }

    const int nl = t >> 4;          // node within block (0..15)
    const int c0 = (t & 15) * 8;    // column group

    u64 au[3][4], av[3][4];
    #pragma unroll
    for (int c = 0; c < 3; c++)
        #pragma unroll
        for (int j = 0; j < 4; j++) { au[c][j] = 0ull; av[c][j] = 0ull; }

    for (int k0 = 0; k0 < D; k0 += 16) {
        __syncthreads();
        for (int k = t; k < 16 * 32; k += 256) {
            int row = k >> 5, c4 = k & 31;
            *(float4*)(&sU[row][c4 * 4]) = __ldg((const float4*)(U_W + (k0 + row) * D + c4 * 4));
            *(float4*)(&sV[row][c4 * 4]) = __ldg((const float4*)(V_W + (k0 + row) * D + c4 * 4));
        }
        __syncthreads();
        #pragma unroll
        for (int kk = 0; kk < 16; kk++) {
            float4 a = *(const float4*)(&sAt[k0 + kk][nl * 4]);
            u64 d0 = pk2(a.x, a.x), d1 = pk2(a.y, a.y), d2 = pk2(a.z, a.z);
            ulonglong2 qu0 = *(const ulonglong2*)(&sU[kk][c0]);
            ulonglong2 qu1 = *(const ulonglong2*)(&sU[kk][c0 + 4]);
            ulonglong2 qv0 = *(const ulonglong2*)(&sV[kk][c0]);
            ulonglong2 qv1 = *(const ulonglong2*)(&sV[kk][c0 + 4]);
            u64 bu[4] = {qu0.x, qu0.y, qu1.x, qu1.y};
            u64 bv[4] = {qv0.x, qv0.y, qv1.x, qv1.y};
            #pragma unroll
            for (int j = 0; j < 4; j++) {
                fma2(au[0][j], d0, bu[j]);
                fma2(au[1][j], d1, bu[j]);
                fma2(au[2][j], d2, bu[j]);
                fma2(av[0][j], d0, bv[j]);
                fma2(av[1][j], d1, bv[j]);
                fma2(av[2][j], d2, bv[j]);
            }
        }
    }

    int node = nb0 + nl;
    if (node < NNODES) {
        float uvv[8], vnv[8];
        #pragma unroll
        for (int j = 0; j < 4; j++) {
            float2 A0 = upk2(au[0][j]), A1 = upk2(au[1][j]), A2 = upk2(au[2][j]);
            float2 B0 = upk2(av[0][j]), B1 = upk2(av[1][j]), B2 = upk2(av[2][j]);
            uvv[2 * j]     = A0.x * B0.x + A1.x * B1.x + A2.x * B2.x;
            uvv[2 * j + 1] = A0.y * B0.y + A1.y * B1.y + A2.y * B2.y;
            vnv[2 * j]     = sqrtf(B0.x * B0.x + B1.x * B1.x + B2.x * B2.x);
            vnv[2 * j + 1] = sqrtf(B0.y * B0.y + B1.y * B1.y + B2.y * B2.y);
        }
        float4* du = (float4*)(g_UV + (size_t)node * D + c0);
        float4* dv = (float4*)(g_Vn + (size_t)node * D + c0);
        du[0] = make_float4(uvv[0], uvv[1], uvv[2], uvv[3]);
        du[1] = make_float4(uvv[4], uvv[5], uvv[6], uvv[7]);
        dv[0] = make_float4(vnv[0], vnv[1], vnv[2], vnv[3]);
        dv[1] = make_float4(vnv[4], vnv[5], vnv[6], vnv[7]);
    }
}

// ---------------- node update MLP + segment-sum ----------------
__global__ __launch_bounds__(128) void update_kernel(
    const float* __restrict__ upd_W1, const float* __restrict__ upd_b1,
    const float* __restrict__ upd_W2, const float* __restrict__ upd_b2,
    const int* __restrict__ node_graph_index)
{
    __shared__ float sA[32][260];
    __shared__ float sW[32][264];
    const int t = threadIdx.x;
    const int n0 = blockIdx.x * 32;

    for (int k = t; k < 32 * 64; k += 128) {
        int row = k >> 6, c4 = k & 63;
        int n = n0 + row;
        float4 v = make_float4(0.f, 0.f, 0.f, 0.f);
        if (n < NNODES) {
            if (c4 < 32) {
                v = ((const float4*)(g_Vn + (size_t)n * D))[c4];
            } else {
                float4 s0 = ((const float4*)(g_state0 + (size_t)n * D))[c4 - 32];
                float4 s1 = ((const float4*)(g_state_acc + (size_t)n * D))[c4 - 32];
                v = make_float4(s0.x + s1.x, s0.y + s1.y, s0.z + s1.z, s0.w + s1.w);
            }
        }
        *(float4*)(&sA[row][c4 * 4]) = v;
    }

    const int ty = t >> 4;
    const int tx = t & 15;
    const int r0 = ty * 4, c0 = tx * 8;

    u64 acc[4][4];
    #pragma unroll
    for (int i = 0; i < 4; i++)
        #pragma unroll
        for (int j = 0; j < 4; j++) acc[i][j] = 0ull;

    for (int k0 = 0; k0 < 2 * D; k0 += 32) {
        __syncthreads();
        for (int k = t; k < 32 * 32; k += 128) {
            int row = k >> 5, c4 = k & 31;
            *(float4*)(&sW[row][c4 * 4]) = __ldg((const float4*)(upd_W1 + (k0 + row) * D + c4 * 4));
        }
        __syncthreads();
        for (int kk = 0; kk < 32; kk++) {
            u64 ad[4];
            #pragma unroll
            for (int i = 0; i < 4; i++) {
                float a = sA[r0 + i][k0 + kk];
                ad[i] = pk2(a, a);
            }
            ulonglong2 q0 = *(const ulonglong2*)(&sW[kk][c0]);
            ulonglong2 q1 = *(const ulonglong2*)(&sW[kk][c0 + 4]);
            u64 bp[4] = {q0.x, q0.y, q1.x, q1.y};
            #pragma unroll
            for (int i = 0; i < 4; i++)
                #pragma unroll
                for (int j = 0; j < 4; j++) fma2(acc[i][j], ad[i], bp[j]);
        }
    }
    __syncthreads();
    #pragma unroll
    for (int j = 0; j < 4; j++) {
        float bias0 = __ldg(&upd_b1[c0 + 2 * j]);
        float bias1 = __ldg(&upd_b1[c0 + 2 * j + 1]);
        #pragma unroll
        for (int i = 0; i < 4; i++) {
            float2 v = upk2(acc[i][j]);
            sA[r0 + i][c0 + 2 * j] = silu_f(v.x + bias0);
            sA[r0 + i][c0 + 2 * j + 1] = silu_f(v.y + bias1);
        }
    }
    __syncthreads();

    u64 asv[4][4], ass[4][4];
    #pragma unroll
    for (int i = 0; i < 4; i++)
        #pragma unroll
        for (int j = 0; j < 4; j++) { asv[i][j] = 0ull; ass[i][j] = 0ull; }

    for (int k0 = 0; k0 < D; k0 += 32) {
        __syncthreads();
        for (int k = t; k < 32 * 64; k += 128) {
            int row = k >> 6, c4 = k & 63;
            *(float4*)(&sW[row][c4 * 4]) = __ldg((const float4*)(upd_W2 + (k0 + row) * 384 + 128 + c4 * 4));
        }
        __syncthreads();
        for (int kk = 0; kk < 32; kk++) {
            u64 ad[4];
            #pragma unroll
            for (int i = 0; i < 4; i++) {
                float a = sA[r0 + i][k0 + kk];
                ad[i] = pk2(a, a);
            }
            ulonglong2 q0 = *(const ulonglong2*)(&sW[kk][c0]);
            ulonglong2 q1 = *(const ulonglong2*)(&sW[kk][c0 + 4]);
            ulonglong2 q2 = *(const ulonglong2*)(&sW[kk][128 + c0]);
            ulonglong2 q3 = *(const ulonglong2*)(&sW[kk][128 + c0 + 4]);
            u64 bsv[4] = {q0.x, q0.y, q1.x, q1.y};
            u64 bss[4] = {q2.x, q2.y, q3.x, q3.y};
            #pragma unroll
            for (int i = 0; i < 4; i++)
                #pragma unroll
                for (int j = 0; j < 4; j++) {
                    fma2(asv[i][j], ad[i], bsv[j]);
                    fma2(ass[i][j], ad[i], bss[j]);
                }
        }
    }

    int base = __ldg(&node_graph_index[0]);
    #pragma unroll
    for (int i = 0; i < 4; i++) {
        int n = n0 + r0 + i;
        if (n < NNODES) {
            int g = __ldg(&node_graph_index[n]) - base;
            float* dst = g_graph + (size_t)g * D + c0;
            float vals[8];
            #pragma unroll
            for (int j = 0; j < 4; j++) {
                float2 sv = upk2(asv[i][j]);
                float2 ss = upk2(ass[i][j]);
                float uv0 = g_UV[(size_t)n * D + c0 + 2 * j];
                float uv1 = g_UV[(size_t)n * D + c0 + 2 * j + 1];
                float a_sv0 = sv.x + __ldg(&upd_b2[D + c0 + 2 * j]);
                float a_sv1 = sv.y + __ldg(&upd_b2[D + c0 + 2 * j + 1]);
                float a_ss0 = ss.x + __ldg(&upd_b2[2 * D + c0 + 2 * j]);
                float a_ss1 = ss.y + __ldg(&upd_b2[2 * D + c0 + 2 * j + 1]);
                vals[2 * j]     = sA[r0 + i][D + c0 + 2 * j]     + uv0 * a_sv0 + a_ss0;
                vals[2 * j + 1] = sA[r0 + i][D + c0 + 2 * j + 1] + uv1 * a_sv1 + a_ss1;
            }
            atomicAdd((float4*)dst,       make_float4(vals[0], vals[1], vals[2], vals[3]));
            atomicAdd((float4*)(dst + 4), make_float4(vals[4], vals[5], vals[6], vals[7]));
        }
    }
}

// ---------------- output MLP: 512 graphs ----------------
__global__ void out_kernel(
    const float* __restrict__ out_W1, const float* __restrict__ out_b1,
    const float* __restrict__ out_W2, const float* __restrict__ out_b2,
    float* __restrict__ out)
{
    __shared__ float sG[D];
    __shared__ float sRed[D];
    const int g = blockIdx.x;
    const int t = threadIdx.x;
    sG[t] = g_graph[(size_t)g * D + t];
    __syncthreads();
    float x = 0.f;
    #pragma unroll 8
    for (int k = 0; k < D; k++) x += sG[k] * __ldg(&out_W1[k * D + t]);
    x += __ldg(&out_b1[t]);
    float p = silu_f(x) * __ldg(&out_W2[t]);
    sRed[t] = p;
    __syncthreads();
    for (int s = 64; s > 0; s >>= 1) {
        if (t < s) sRed[t] += sRed[t + s];
        __syncthreads();
    }
    if (t == 0) out[g] = sRed[0] + __ldg(&out_b2[0]);
}

// ---------------- launch ----------------
extern "C" void kernel_launch(void* const* d_in, const int* in_sizes, int n_in,
                              void* d_out, int out_size)
{
    const float* edge_vec  = (const float*)d_in[0];
    const float* embedding = (const float*)d_in[1];
    const float* phi_W1 = (const float*)d_in[2];
    const float* phi_b1 = (const float*)d_in[3];
    const float* phi_W2 = (const float*)d_in[4];
    const float* phi_b2 = (const float*)d_in[5];
    const float* filt_W = (const float*)d_in[6];
    const float* filt_b = (const float*)d_in[7];
    const float* upd_W1 = (const float*)d_in[8];
    const float* upd_b1 = (const float*)d_in[9];
    const float* upd_W2 = (const float*)d_in[10];
    const float* upd_b2 = (const float*)d_in[11];
    const float* out_W1 = (const float*)d_in[12];
    const float* out_b1 = (const float*)d_in[13];
    const float* out_W2 = (const float*)d_in[14];
    const float* out_b2 = (const float*)d_in[15];
    const float* U_W    = (const float*)d_in[16];
    const float* V_W    = (const float*)d_in[17];
    const int* atom_types = (const int*)d_in[18];
    const int* node_from  = (const int*)d_in[19];
    const int* node_to    = (const int*)d_in[20];
    const int* node_graph_index = (const int*)d_in[21];
    float* out = (float*)d_out;

    init_kernel<<<2048, 256>>>(embedding, atom_types);
    node_phi_kernel<<<(NNODES + 63) / 64, 128>>>(phi_W1, phi_b1, phi_W2, phi_b2);
    edge_kernel<<<NEDGES / 8, 256>>>(edge_vec, filt_W, filt_b, node_from, node_to);
    uv_kernel<<<(NNODES + 15) / 16, 256>>>(U_W, V_W);
    update_kernel<<<(NNODES + 31) / 32, 128>>>(upd_W1, upd_b1, upd_W2, upd_b2, node_graph_index);
    out_kernel<<<NGRAPHS, D>>>(out_W1, out_b1, out_W2, out_b2, out);
}

// round 6
// speedup vs baseline: 1.1627x; 1.1465x over previous
#include <cuda_runtime.h>
#include <math.h>

#define D 128
#define NRBF 20
#define NNODES 25000
#define NEDGES 250000
#define NGRAPHS 512

// ---------------- scratch (device globals; no allocation) ----------------
__device__ float g_state0[NNODES * D];
__device__ float g_state_acc[NNODES * D];
__device__ float g_state_vec[NNODES * 3 * D];
__device__ float g_phi[NNODES * 2 * D];         // per-node phi cols 128..383 (m2|m3)
__device__ float g_UV[NNODES * D];
__device__ float g_Vn[NNODES * D];
__device__ float g_graph[NGRAPHS * D];

typedef unsigned long long u64;

__device__ __forceinline__ float silu_f(float x) {
    return x / (1.0f + __expf(-x));
}

__device__ __forceinline__ u64 pk2(float lo, float hi) {
    u64 r;
    asm("mov.b64 %0, {%1, %2};" : "=l"(r) : "r"(__float_as_uint(lo)), "r"(__float_as_uint(hi)));
    return r;
}
__device__ __forceinline__ float2 upk2(u64 v) {
    unsigned lo, hi;
    asm("mov.b64 {%0, %1}, %2;" : "=r"(lo), "=r"(hi) : "l"(v));
    return make_float2(__uint_as_float(lo), __uint_as_float(hi));
}
__device__ __forceinline__ void fma2(u64& acc, u64 a, u64 b) {
    asm("fma.rn.f32x2 %0, %1, %2, %0;" : "+l"(acc) : "l"(a), "l"(b));
}

// ---------------- init ----------------
__global__ void init_kernel(const float* __restrict__ emb, const int* __restrict__ atype) {
    int stride = gridDim.x * blockDim.x;
    int total = NNODES * 3 * D;
    for (int idx = blockIdx.x * blockDim.x + threadIdx.x; idx < total; idx += stride) {
        g_state_vec[idx] = 0.0f;
        if (idx < NNODES * D) {
            int n = idx >> 7;
            int j = idx & 127;
            g_state0[idx] = emb[atype[n] * D + j];
            g_state_acc[idx] = 0.0f;
        }
        if (idx < NGRAPHS * D) g_graph[idx] = 0.0f;
    }
}

// ---------------- per-node phi MLP ----------------
__global__ __launch_bounds__(128) void node_phi_kernel(
    const float* __restrict__ phi_W1, const float* __restrict__ phi_b1,
    const float* __restrict__ phi_W2, const float* __restrict__ phi_b2)
{
    __shared__ float sA[64][132];
    __shared__ float sW[32][132];
    const int t = threadIdx.x;
    const int n0 = blockIdx.x * 64;

    for (int k = t; k < 64 * 32; k += 128) {
        int row = k >> 5, c4 = k & 31;
        int n = n0 + row;
        float4 v = make_float4(0.f, 0.f, 0.f, 0.f);
        if (n < NNODES) v = ((const float4*)(g_state0 + (size_t)n * D))[c4];
        *(float4*)(&sA[row][c4 * 4]) = v;
    }

    const int ty = t >> 4;
    const int tx = t & 15;
    const int r0 = ty * 8, c0 = tx * 8;

    u64 acc[8][4];
    #pragma unroll
    for (int i = 0; i < 8; i++)
        #pragma unroll
        for (int j = 0; j < 4; j++) acc[i][j] = 0ull;

    for (int k0 = 0; k0 < D; k0 += 32) {
        __syncthreads();
        for (int k = t; k < 32 * 32; k += 128) {
            int row = k >> 5, c4 = k & 31;
            *(float4*)(&sW[row][c4 * 4]) = __ldg((const float4*)(phi_W1 + (k0 + row) * D + c4 * 4));
        }
        __syncthreads();
        for (int kk = 0; kk < 32; kk++) {
            u64 ad[8];
            #pragma unroll
            for (int i = 0; i < 8; i++) {
                float a = sA[r0 + i][k0 + kk];
                ad[i] = pk2(a, a);
            }
            ulonglong2 q0 = *(const ulonglong2*)(&sW[kk][c0]);
            ulonglong2 q1 = *(const ulonglong2*)(&sW[kk][c0 + 4]);
            u64 bp[4] = {q0.x, q0.y, q1.x, q1.y};
            #pragma unroll
            for (int i = 0; i < 8; i++)
                #pragma unroll
                for (int j = 0; j < 4; j++) fma2(acc[i][j], ad[i], bp[j]);
        }
    }
    __syncthreads();
    #pragma unroll
    for (int j = 0; j < 4; j++) {
        float bias0 = __ldg(&phi_b1[c0 + 2 * j]);
        float bias1 = __ldg(&phi_b1[c0 + 2 * j + 1]);
        #pragma unroll
        for (int i = 0; i < 8; i++) {
            float2 v = upk2(acc[i][j]);
            sA[r0 + i][c0 + 2 * j] = silu_f(v.x + bias0);
            sA[r0 + i][c0 + 2 * j + 1] = silu_f(v.y + bias1);
        }
    }
    __syncthreads();

    #pragma unroll 1
    for (int half = 0; half < 2; half++) {
        const int cb = D + half * D;
        u64 acc2[8][4];
        #pragma unroll
        for (int i = 0; i < 8; i++)
            #pragma unroll
            for (int j = 0; j < 4; j++) acc2[i][j] = 0ull;

        for (int k0 = 0; k0 < D; k0 += 32) {
            __syncthreads();
            for (int k = t; k < 32 * 32; k += 128) {
                int row = k >> 5, c4 = k & 31;
                *(float4*)(&sW[row][c4 * 4]) = __ldg((const float4*)(phi_W2 + (k0 + row) * 384 + cb + c4 * 4));
            }
            __syncthreads();
            for (int kk = 0; kk < 32; kk++) {
                u64 ad[8];
                #pragma unroll
                for (int i = 0; i < 8; i++) {
                    float a = sA[r0 + i][k0 + kk];
                    ad[i] = pk2(a, a);
                }
                ulonglong2 q0 = *(const ulonglong2*)(&sW[kk][c0]);
                ulonglong2 q1 = *(const ulonglong2*)(&sW[kk][c0 + 4]);
                u64 bp[4] = {q0.x, q0.y, q1.x, q1.y};
                #pragma unroll
                for (int i = 0; i < 8; i++)
                    #pragma unroll
                    for (int j = 0; j < 4; j++) fma2(acc2[i][j], ad[i], bp[j]);
            }
        }

        #pragma unroll
        for (int i = 0; i < 8; i++) {
            int n = n0 + r0 + i;
            if (n < NNODES) {
                float2 p0 = upk2(acc2[i][0]);
                float2 p1 = upk2(acc2[i][1]);
                float2 p2 = upk2(acc2[i][2]);
                float2 p3 = upk2(acc2[i][3]);
                float4* dst = (float4*)(g_phi + (size_t)n * 256 + half * D + c0);
                dst[0] = make_float4(p0.x + __ldg(&phi_b2[cb + c0 + 0]),
                                     p0.y + __ldg(&phi_b2[cb + c0 + 1]),
                                     p1.x + __ldg(&phi_b2[cb + c0 + 2]),
                                     p1.y + __ldg(&phi_b2[cb + c0 + 3]));
                dst[1] = make_float4(p2.x + __ldg(&phi_b2[cb + c0 + 4]),
                                     p2.y + __ldg(&phi_b2[cb + c0 + 5]),
                                     p3.x + __ldg(&phi_b2[cb + c0 + 6]),
                                     p3.y + __ldg(&phi_b2[cb + c0 + 7]));
            }
        }
    }
}

// ---------------- edge kernel: RBF filter + gather phi[from] + scatter ----------------
__global__ __launch_bounds__(256) void edge_kernel(
    const float* __restrict__ edge_vec,
    const float* __restrict__ filt_W, const float* __restrict__ filt_b,
    const int* __restrict__ node_from, const int* __restrict__ node_to)
{
    __shared__ float sRbf[8][20];
    __shared__ float sFc[8];
    __shared__ float sDist[8];
    __shared__ float sNorm[8][3];
    __shared__ int   sFrom[8];
    __shared__ int   sTo[8];

    const int t = threadIdx.x;
    const int e0 = blockIdx.x * 8;
    const float PI = 3.14159265358979323846f;

    if (t < 8) {
        int e = e0 + t;
        float x = edge_vec[3 * e + 0];
        float y = edge_vec[3 * e + 1];
        float z = edge_vec[3 * e + 2];
        float d = sqrtf(x * x + y * y + z * z);
        float inv = 1.0f / d;
        float fcv = (d < 10.0f) ? 0.5f * (cosf(PI * d * 0.1f) + 1.0f) : 0.0f;
        sDist[t] = d;
        sFc[t] = fcv * inv;
        sNorm[t][0] = x * inv; sNorm[t][1] = y * inv; sNorm[t][2] = z * inv;
        sFrom[t] = node_from[e];
        sTo[t] = node_to[e];
    }
    __syncthreads();
    if (t < 160) {
        int le = t / 20, r = t % 20;
        sRbf[le][r] = sinf((float)(r + 1) * PI * sDist[le] * 0.1f) * sFc[le];
    }
    __syncthreads();

    const int le = t >> 5;
    const int j0 = (t & 31) << 3;
    const float fc = sFc[le] * sDist[le];

    float w[8];
    #pragma unroll
    for (int j = 0; j < 8; j++) w[j] = fc * __ldg(&filt_b[128 + j0 + j]);
    #pragma unroll
    for (int r = 0; r < NRBF; r++) {
        float a = sRbf[le][r];
        float4 b0 = __ldg((const float4*)(filt_W + r * 384 + 128 + j0));
        float4 b1 = __ldg((const float4*)(filt_W + r * 384 + 128 + j0 + 4));
        w[0] += a * b0.x; w[1] += a * b0.y; w[2] += a * b0.z; w[3] += a * b0.w;
        w[4] += a * b1.x; w[5] += a * b1.y; w[6] += a * b1.z; w[7] += a * b1.w;
    }

    const float4* ph = (const float4*)(g_phi + (size_t)sFrom[le] * 256 + j0);
    float4 p0 = ph[0];
    float4 p1 = ph[1];
    float pf[8];
    pf[0] = p0.x * w[0]; pf[1] = p0.y * w[1]; pf[2] = p0.z * w[2]; pf[3] = p0.w * w[3];
    pf[4] = p1.x * w[4]; pf[5] = p1.y * w[5]; pf[6] = p1.z * w[6]; pf[7] = p1.w * w[7];

    const int to = sTo[le];
    if (j0 < 128) {
        float4* dst = (float4*)(g_state_acc + (size_t)to * D + j0);
        atomicAdd(dst,     make_float4(pf[0], pf[1], pf[2], pf[3]));
        atomicAdd(dst + 1, make_float4(pf[4], pf[5], pf[6], pf[7]));
    } else {
        const int jj = j0 - 128;
        float n0 = sNorm[le][0], n1 = sNorm[le][1], n2 = sNorm[le][2];
        float* base = g_state_vec + (size_t)to * (3 * D) + jj;
        atomicAdd((float4*)(base),             make_float4(n0 * pf[0], n0 * pf[1], n0 * pf[2], n0 * pf[3]));
        atomicAdd((float4*)(base + 4),         make_float4(n0 * pf[4], n0 * pf[5], n0 * pf[6], n0 * pf[7]));
        atomicAdd((float4*)(base + D),         make_float4(n1 * pf[0], n1 * pf[1], n1 * pf[2], n1 * pf[3]));
        atomicAdd((float4*)(base + D + 4),     make_float4(n1 * pf[4], n1 * pf[5], n1 * pf[6], n1 * pf[7]));
        atomicAdd((float4*)(base + 2 * D),     make_float4(n2 * pf[0], n2 * pf[1], n2 * pf[2], n2 * pf[3]));
        atomicAdd((float4*)(base + 2 * D + 4), make_float4(n2 * pf[4], n2 * pf[5], n2 * pf[6], n2 * pf[7]));
    }
}

// ---------------- fused UV kernel: Up/Vp GEMM + UV/Vn reduce ----------------
// 32 nodes / block, 256 threads, 2 blocks/SM. Thread tile: 4 nodes x 3 comps x 4 cols.
// A staged per 16-k tile (transposed, broadcast LDS.128); U/V per 16-k tile.
// 48 FMA2 per kk per thread vs 6 LDS.128 (4 broadcast + 2 contiguous).
__global__ __launch_bounds__(256, 2) void uv_kernel(
    const float* __restrict__ U_W, const float* __restrict__ V_W)
{
    __shared__ float sAt[16][132];   // [kk][node*4+comp], pad col 3
    __shared__ float sU[16][132];
    __shared__ float sV[16][132];
    const int t = threadIdx.x;
    const int nb0 = blockIdx.x * 32;
    const int rb = nb0 * 3;
    const int NR = NNODES * 3;

    const int ng = t >> 5;          // node group 0..7: nodes ng, ng+8, ng+16, ng+24
    const int c0 = (t & 31) * 4;    // 4-col group

    u64 acc_u[4][3][2], acc_v[4][3][2];
    #pragma unroll
    for (int m = 0; m < 4; m++)
        #pragma unroll
        for (int c = 0; c < 3; c++)
            #pragma unroll
            for (int j = 0; j < 2; j++) { acc_u[m][c][j] = 0ull; acc_v[m][c][j] = 0ull; }

    for (int k0 = 0; k0 < D; k0 += 16) {
        __syncthreads();
        // stage A tile: 96 rows x 16 k, transposed into sAt[k][nl*4+comp]
        for (int idx = t; idx < 96 * 16; idx += 256) {
            int row = idx >> 4;          // 0..95
            int k = idx & 15;
            int r = rb + row;
            float v = (r < NR) ? g_state_vec[(size_t)r * D + k0 + k] : 0.f;
            int nl = row / 3, comp = row - nl * 3;
            sAt[k][nl * 4 + comp] = v;
        }
        // stage U/V tiles: 16 rows x 32 float4
        for (int k = t; k < 16 * 32; k += 256) {
            int row = k >> 5, c4 = k & 31;
            *(float4*)(&sU[row][c4 * 4]) = __ldg((const float4*)(U_W + (k0 + row) * D + c4 * 4));
            *(float4*)(&sV[row][c4 * 4]) = __ldg((const float4*)(V_W + (k0 + row) * D + c4 * 4));
        }
        __syncthreads();
        #pragma unroll
        for (int kk = 0; kk < 16; kk++) {
            ulonglong2 qu = *(const ulonglong2*)(&sU[kk][c0]);
            ulonglong2 qv = *(const ulonglong2*)(&sV[kk][c0]);
            u64 bu[2] = {qu.x, qu.y};
            u64 bv[2] = {qv.x, qv.y};
            #pragma unroll
            for (int m = 0; m < 4; m++) {
                float4 a = *(const float4*)(&sAt[kk][(ng + 8 * m) * 4]);
                u64 d0 = pk2(a.x, a.x), d1 = pk2(a.y, a.y), d2 = pk2(a.z, a.z);
                #pragma unroll
                for (int j = 0; j < 2; j++) {
                    fma2(acc_u[m][0][j], d0, bu[j]);
                    fma2(acc_u[m][1][j], d1, bu[j]);
                    fma2(acc_u[m][2][j], d2, bu[j]);
                    fma2(acc_v[m][0][j], d0, bv[j]);
                    fma2(acc_v[m][1][j], d1, bv[j]);
                    fma2(acc_v[m][2][j], d2, bv[j]);
                }
            }
        }
    }

    #pragma unroll
    for (int m = 0; m < 4; m++) {
        int node = nb0 + ng + 8 * m;
        if (node < NNODES) {
            float uvv[4], vnv[4];
            #pragma unroll
            for (int j = 0; j < 2; j++) {
                float2 U0 = upk2(acc_u[m][0][j]), U1 = upk2(acc_u[m][1][j]), U2 = upk2(acc_u[m][2][j]);
                float2 V0 = upk2(acc_v[m][0][j]), V1 = upk2(acc_v[m][1][j]), V2 = upk2(acc_v[m][2][j]);
                uvv[2 * j]     = U0.x * V0.x + U1.x * V1.x + U2.x * V2.x;
                uvv[2 * j + 1] = U0.y * V0.y + U1.y * V1.y + U2.y * V2.y;
                vnv[2 * j]     = sqrtf(V0.x * V0.x + V1.x * V1.x + V2.x * V2.x);
                vnv[2 * j + 1] = sqrtf(V0.y * V0.y + V1.y * V1.y + V2.y * V2.y);
            }
            *(float4*)(g_UV + (size_t)node * D + c0) = make_float4(uvv[0], uvv[1], uvv[2], uvv[3]);
            *(float4*)(g_Vn + (size_t)node * D + c0) = make_float4(vnv[0], vnv[1], vnv[2], vnv[3]);
        }
    }
}

// ---------------- node update MLP + segment-sum ----------------
__global__ __launch_bounds__(128) void update_kernel(
    const float* __restrict__ upd_W1, const float* __restrict__ upd_b1,
    const float* __restrict__ upd_W2, const float* __restrict__ upd_b2,
    const int* __restrict__ node_graph_index)
{
    __shared__ float sA[32][260];
    __shared__ float sW[32][264];
    const int t = threadIdx.x;
    const int n0 = blockIdx.x * 32;

    for (int k = t; k < 32 * 64; k += 128) {
        int row = k >> 6, c4 = k & 63;
        int n = n0 + row;
        float4 v = make_float4(0.f, 0.f, 0.f, 0.f);
        if (n < NNODES) {
            if (c4 < 32) {
                v = ((const float4*)(g_Vn + (size_t)n * D))[c4];
            } else {
                float4 s0 = ((const float4*)(g_state0 + (size_t)n * D))[c4 - 32];
                float4 s1 = ((const float4*)(g_state_acc + (size_t)n * D))[c4 - 32];
                v = make_float4(s0.x + s1.x, s0.y + s1.y, s0.z + s1.z, s0.w + s1.w);
            }
        }
        *(float4*)(&sA[row][c4 * 4]) = v;
    }

    const int ty = t >> 4;
    const int tx = t & 15;
    const int r0 = ty * 4, c0 = tx * 8;

    u64 acc[4][4];
    #pragma unroll
    for (int i = 0; i < 4; i++)
        #pragma unroll
        for (int j = 0; j < 4; j++) acc[i][j] = 0ull;

    for (int k0 = 0; k0 < 2 * D; k0 += 32) {
        __syncthreads();
        for (int k = t; k < 32 * 32; k += 128) {
            int row = k >> 5, c4 = k & 31;
            *(float4*)(&sW[row][c4 * 4]) = __ldg((const float4*)(upd_W1 + (k0 + row) * D + c4 * 4));
        }
        __syncthreads();
        for (int kk = 0; kk < 32; kk++) {
            u64 ad[4];
            #pragma unroll
            for (int i = 0; i < 4; i++) {
                float a = sA[r0 + i][k0 + kk];
                ad[i] = pk2(a, a);
            }
            ulonglong2 q0 = *(const ulonglong2*)(&sW[kk][c0]);
            ulonglong2 q1 = *(const ulonglong2*)(&sW[kk][c0 + 4]);
            u64 bp[4] = {q0.x, q0.y, q1.x, q1.y};
            #pragma unroll
            for (int i = 0; i < 4; i++)
                #pragma unroll
                for (int j = 0; j < 4; j++) fma2(acc[i][j], ad[i], bp[j]);
        }
    }
    __syncthreads();
    #pragma unroll
    for (int j = 0; j < 4; j++) {
        float bias0 = __ldg(&upd_b1[c0 + 2 * j]);
        float bias1 = __ldg(&upd_b1[c0 + 2 * j + 1]);
        #pragma unroll
        for (int i = 0; i < 4; i++) {
            float2 v = upk2(acc[i][j]);
            sA[r0 + i][c0 + 2 * j] = silu_f(v.x + bias0);
            sA[r0 + i][c0 + 2 * j + 1] = silu_f(v.y + bias1);
        }
    }
    __syncthreads();

    u64 asv[4][4], ass[4][4];
    #pragma unroll
    for (int i = 0; i < 4; i++)
        #pragma unroll
        for (int j = 0; j < 4; j++) { asv[i][j] = 0ull; ass[i][j] = 0ull; }

    for (int k0 = 0; k0 < D; k0 += 32) {
        __syncthreads();
        for (int k = t; k < 32 * 64; k += 128) {
            int row = k >> 6, c4 = k & 63;
            *(float4*)(&sW[row][c4 * 4]) = __ldg((const float4*)(upd_W2 + (k0 + row) * 384 + 128 + c4 * 4));
        }
        __syncthreads();
        for (int kk = 0; kk < 32; kk++) {
            u64 ad[4];
            #pragma unroll
            for (int i = 0; i < 4; i++) {
                float a = sA[r0 + i][k0 + kk];
                ad[i] = pk2(a, a);
            }
            ulonglong2 q0 = *(const ulonglong2*)(&sW[kk][c0]);
            ulonglong2 q1 = *(const ulonglong2*)(&sW[kk][c0 + 4]);
            ulonglong2 q2 = *(const ulonglong2*)(&sW[kk][128 + c0]);
            ulonglong2 q3 = *(const ulonglong2*)(&sW[kk][128 + c0 + 4]);
            u64 bsv[4] = {q0.x, q0.y, q1.x, q1.y};
            u64 bss[4] = {q2.x, q2.y, q3.x, q3.y};
            #pragma unroll
            for (int i = 0; i < 4; i++)
                #pragma unroll
                for (int j = 0; j < 4; j++) {
                    fma2(asv[i][j], ad[i], bsv[j]);
                    fma2(ass[i][j], ad[i], bss[j]);
                }
        }
    }

    int base = __ldg(&node_graph_index[0]);
    #pragma unroll
    for (int i = 0; i < 4; i++) {
        int n = n0 + r0 + i;
        if (n < NNODES) {
            int g = __ldg(&node_graph_index[n]) - base;
            float* dst = g_graph + (size_t)g * D + c0;
            float vals[8];
            #pragma unroll
            for (int j = 0; j < 4; j++) {
                float2 sv = upk2(asv[i][j]);
                float2 ss = upk2(ass[i][j]);
                float uv0 = g_UV[(size_t)n * D + c0 + 2 * j];
                float uv1 = g_UV[(size_t)n * D + c0 + 2 * j + 1];
                float a_sv0 = sv.x + __ldg(&upd_b2[D + c0 + 2 * j]);
                float a_sv1 = sv.y + __ldg(&upd_b2[D + c0 + 2 * j + 1]);
                float a_ss0 = ss.x + __ldg(&upd_b2[2 * D + c0 + 2 * j]);
                float a_ss1 = ss.y + __ldg(&upd_b2[2 * D + c0 + 2 * j + 1]);
                vals[2 * j]     = sA[r0 + i][D + c0 + 2 * j]     + uv0 * a_sv0 + a_ss0;
                vals[2 * j + 1] = sA[r0 + i][D + c0 + 2 * j + 1] + uv1 * a_sv1 + a_ss1;
            }
            atomicAdd((float4*)dst,       make_float4(vals[0], vals[1], vals[2], vals[3]));
            atomicAdd((float4*)(dst + 4), make_float4(vals[4], vals[5], vals[6], vals[7]));
        }
    }
}

// ---------------- output MLP: 512 graphs ----------------
__global__ void out_kernel(
    const float* __restrict__ out_W1, const float* __restrict__ out_b1,
    const float* __restrict__ out_W2, const float* __restrict__ out_b2,
    float* __restrict__ out)
{
    __shared__ float sG[D];
    __shared__ float sRed[D];
    const int g = blockIdx.x;
    const int t = threadIdx.x;
    sG[t] = g_graph[(size_t)g * D + t];
    __syncthreads();
    float x = 0.f;
    #pragma unroll 8
    for (int k = 0; k < D; k++) x += sG[k] * __ldg(&out_W1[k * D + t]);
    x += __ldg(&out_b1[t]);
    float p = silu_f(x) * __ldg(&out_W2[t]);
    sRed[t] = p;
    __syncthreads();
    for (int s = 64; s > 0; s >>= 1) {
        if (t < s) sRed[t] += sRed[t + s];
        __syncthreads();
    }
    if (t == 0) out[g] = sRed[0] + __ldg(&out_b2[0]);
}

// ---------------- launch ----------------
extern "C" void kernel_launch(void* const* d_in, const int* in_sizes, int n_in,
                              void* d_out, int out_size)
{
    const float* edge_vec  = (const float*)d_in[0];
    const float* embedding = (const float*)d_in[1];
    const float* phi_W1 = (const float*)d_in[2];
    const float* phi_b1 = (const float*)d_in[3];
    const float* phi_W2 = (const float*)d_in[4];
    const float* phi_b2 = (const float*)d_in[5];
    const float* filt_W = (const float*)d_in[6];
    const float* filt_b = (const float*)d_in[7];
    const float* upd_W1 = (const float*)d_in[8];
    const float* upd_b1 = (const float*)d_in[9];
    const float* upd_W2 = (const float*)d_in[10];
    const float* upd_b2 = (const float*)d_in[11];
    const float* out_W1 = (const float*)d_in[12];
    const float* out_b1 = (const float*)d_in[13];
    const float* out_W2 = (const float*)d_in[14];
    const float* out_b2 = (const float*)d_in[15];
    const float* U_W    = (const float*)d_in[16];
    const float* V_W    = (const float*)d_in[17];
    const int* atom_types = (const int*)d_in[18];
    const int* node_from  = (const int*)d_in[19];
    const int* node_to    = (const int*)d_in[20];
    const int* node_graph_index = (const int*)d_in[21];
    float* out = (float*)d_out;

    init_kernel<<<2048, 256>>>(embedding, atom_types);
    node_phi_kernel<<<(NNODES + 63) / 64, 128>>>(phi_W1, phi_b1, phi_W2, phi_b2);
    edge_kernel<<<NEDGES / 8, 256>>>(edge_vec, filt_W, filt_b, node_from, node_to);
    uv_kernel<<<(NNODES + 31) / 32, 256>>>(U_W, V_W);
    update_kernel<<<(NNODES + 31) / 32, 128>>>(upd_W1, upd_b1, upd_W2, upd_b2, node_graph_index);
    out_kernel<<<NGRAPHS, D>>>(out_W1, out_b1, out_W2, out_b2, out);
}

// round 7
// speedup vs baseline: 1.5045x; 1.2940x over previous
#include <cuda_runtime.h>
#include <math.h>

#define D 128
#define NRBF 20
#define NNODES 25000
#define NEDGES 250000
#define NGRAPHS 512

// ---------------- scratch (device globals; no allocation) ----------------
__device__ float g_state0[NNODES * D];
__device__ float g_state_acc[NNODES * D];
__device__ float g_state_vec[NNODES * 3 * D];
__device__ float g_phi[NNODES * 2 * D];         // per-node phi cols 128..383 (m2|m3)
__device__ float g_UV[NNODES * D];
__device__ float g_Vn[NNODES * D];
__device__ float g_graph[NGRAPHS * D];

typedef unsigned long long u64;

__device__ __forceinline__ float silu_f(float x) {
    return x / (1.0f + __expf(-x));
}

__device__ __forceinline__ u64 pk2(float lo, float hi) {
    u64 r;
    asm("mov.b64 %0, {%1, %2};" : "=l"(r) : "r"(__float_as_uint(lo)), "r"(__float_as_uint(hi)));
    return r;
}
__device__ __forceinline__ float2 upk2(u64 v) {
    unsigned lo, hi;
    asm("mov.b64 {%0, %1}, %2;" : "=r"(lo), "=r"(hi) : "l"(v));
    return make_float2(__uint_as_float(lo), __uint_as_float(hi));
}
__device__ __forceinline__ void fma2(u64& acc, u64 a, u64 b) {
    asm("fma.rn.f32x2 %0, %1, %2, %0;" : "+l"(acc) : "l"(a), "l"(b));
}

// ---------------- init ----------------
__global__ void init_kernel(const float* __restrict__ emb, const int* __restrict__ atype) {
    int stride = gridDim.x * blockDim.x;
    int total = NNODES * 3 * D;
    for (int idx = blockIdx.x * blockDim.x + threadIdx.x; idx < total; idx += stride) {
        g_state_vec[idx] = 0.0f;
        if (idx < NNODES * D) {
            int n = idx >> 7;
            int j = idx & 127;
            g_state0[idx] = emb[atype[n] * D + j];
            g_state_acc[idx] = 0.0f;
        }
        if (idx < NGRAPHS * D) g_graph[idx] = 0.0f;
    }
}

// ---------------- per-node phi MLP ----------------
__global__ __launch_bounds__(128) void node_phi_kernel(
    const float* __restrict__ phi_W1, const float* __restrict__ phi_b1,
    const float* __restrict__ phi_W2, const float* __restrict__ phi_b2)
{
    __shared__ float sA[64][132];
    __shared__ float sW[32][132];
    const int t = threadIdx.x;
    const int n0 = blockIdx.x * 64;

    for (int k = t; k < 64 * 32; k += 128) {
        int row = k >> 5, c4 = k & 31;
        int n = n0 + row;
        float4 v = make_float4(0.f, 0.f, 0.f, 0.f);
        if (n < NNODES) v = ((const float4*)(g_state0 + (size_t)n * D))[c4];
        *(float4*)(&sA[row][c4 * 4]) = v;
    }

    const int ty = t >> 4;
    const int tx = t & 15;
    const int r0 = ty * 8, c0 = tx * 8;

    u64 acc[8][4];
    #pragma unroll
    for (int i = 0; i < 8; i++)
        #pragma unroll
        for (int j = 0; j < 4; j++) acc[i][j] = 0ull;

    for (int k0 = 0; k0 < D; k0 += 32) {
        __syncthreads();
        for (int k = t; k < 32 * 32; k += 128) {
            int row = k >> 5, c4 = k & 31;
            *(float4*)(&sW[row][c4 * 4]) = __ldg((const float4*)(phi_W1 + (k0 + row) * D + c4 * 4));
        }
        __syncthreads();
        for (int kk = 0; kk < 32; kk++) {
            u64 ad[8];
            #pragma unroll
            for (int i = 0; i < 8; i++) {
                float a = sA[r0 + i][k0 + kk];
                ad[i] = pk2(a, a);
            }
            ulonglong2 q0 = *(const ulonglong2*)(&sW[kk][c0]);
            ulonglong2 q1 = *(const ulonglong2*)(&sW[kk][c0 + 4]);
            u64 bp[4] = {q0.x, q0.y, q1.x, q1.y};
            #pragma unroll
            for (int i = 0; i < 8; i++)
                #pragma unroll
                for (int j = 0; j < 4; j++) fma2(acc[i][j], ad[i], bp[j]);
        }
    }
    __syncthreads();
    #pragma unroll
    for (int j = 0; j < 4; j++) {
        float bias0 = __ldg(&phi_b1[c0 + 2 * j]);
        float bias1 = __ldg(&phi_b1[c0 + 2 * j + 1]);
        #pragma unroll
        for (int i = 0; i < 8; i++) {
            float2 v = upk2(acc[i][j]);
            sA[r0 + i][c0 + 2 * j] = silu_f(v.x + bias0);
            sA[r0 + i][c0 + 2 * j + 1] = silu_f(v.y + bias1);
        }
    }
    __syncthreads();

    #pragma unroll 1
    for (int half = 0; half < 2; half++) {
        const int cb = D + half * D;
        u64 acc2[8][4];
        #pragma unroll
        for (int i = 0; i < 8; i++)
            #pragma unroll
            for (int j = 0; j < 4; j++) acc2[i][j] = 0ull;

        for (int k0 = 0; k0 < D; k0 += 32) {
            __syncthreads();
            for (int k = t; k < 32 * 32; k += 128) {
                int row = k >> 5, c4 = k & 31;
                *(float4*)(&sW[row][c4 * 4]) = __ldg((const float4*)(phi_W2 + (k0 + row) * 384 + cb + c4 * 4));
            }
            __syncthreads();
            for (int kk = 0; kk < 32; kk++) {
                u64 ad[8];
                #pragma unroll
                for (int i = 0; i < 8; i++) {
                    float a = sA[r0 + i][k0 + kk];
                    ad[i] = pk2(a, a);
                }
                ulonglong2 q0 = *(const ulonglong2*)(&sW[kk][c0]);
                ulonglong2 q1 = *(const ulonglong2*)(&sW[kk][c0 + 4]);
                u64 bp[4] = {q0.x, q0.y, q1.x, q1.y};
                #pragma unroll
                for (int i = 0; i < 8; i++)
                    #pragma unroll
                    for (int j = 0; j < 4; j++) fma2(acc2[i][j], ad[i], bp[j]);
            }
        }

        #pragma unroll
        for (int i = 0; i < 8; i++) {
            int n = n0 + r0 + i;
            if (n < NNODES) {
                float2 p0 = upk2(acc2[i][0]);
                float2 p1 = upk2(acc2[i][1]);
                float2 p2 = upk2(acc2[i][2]);
                float2 p3 = upk2(acc2[i][3]);
                float4* dst = (float4*)(g_phi + (size_t)n * 256 + half * D + c0);
                dst[0] = make_float4(p0.x + __ldg(&phi_b2[cb + c0 + 0]),
                                     p0.y + __ldg(&phi_b2[cb + c0 + 1]),
                                     p1.x + __ldg(&phi_b2[cb + c0 + 2]),
                                     p1.y + __ldg(&phi_b2[cb + c0 + 3]));
                dst[1] = make_float4(p2.x + __ldg(&phi_b2[cb + c0 + 4]),
                                     p2.y + __ldg(&phi_b2[cb + c0 + 5]),
                                     p3.x + __ldg(&phi_b2[cb + c0 + 6]),
                                     p3.y + __ldg(&phi_b2[cb + c0 + 7]));
            }
        }
    }
}

// ---------------- edge kernel: smem-staged filter GEMM + gather + scatter ----------------
// 32 edges / block, 256 threads = 8 edge-slots x 32 col-groups; thread loops 4 edges.
// filt_W[:,128:384] staged in smem once per block; filter math in f32x2.
__global__ __launch_bounds__(256) void edge_kernel(
    const float* __restrict__ edge_vec,
    const float* __restrict__ filt_W, const float* __restrict__ filt_b,
    const int* __restrict__ node_from, const int* __restrict__ node_to)
{
    __shared__ float sW[20][264];    // filt_W rows, cols 128..383 (pad)
    __shared__ float sWb[256];       // filt_b[128:384]
    __shared__ float sRbf[32][22];   // rbf * fc / d  (padded)
    __shared__ float sFc[32];        // fc
    __shared__ float sFcInv[32];     // fc / d
    __shared__ float sDist[32];
    __shared__ float sNorm[32][4];
    __shared__ int   sFrom[32];
    __shared__ int   sTo[32];

    const int t = threadIdx.x;
    const int e0 = blockIdx.x * 32;
    const float PI = 3.14159265358979323846f;

    // stage filter weights: 20 rows x 64 float4
    for (int k = t; k < 20 * 64; k += 256) {
        int row = k >> 6, c4 = k & 63;
        *(float4*)(&sW[row][c4 * 4]) = __ldg((const float4*)(filt_W + row * 384 + 128 + c4 * 4));
    }
    if (t < 64) *(float4*)(&sWb[t * 4]) = __ldg((const float4*)(filt_b + 128 + t * 4));

    // per-edge scalars
    if (t < 32) {
        int e = e0 + t;
        float d = 1.f, fcv = 0.f, nx = 0.f, ny = 0.f, nz = 0.f;
        int f = 0, to = 0;
        if (e < NEDGES) {
            float x = edge_vec[3 * e + 0];
            float y = edge_vec[3 * e + 1];
            float z = edge_vec[3 * e + 2];
            d = sqrtf(x * x + y * y + z * z);
            float inv = 1.0f / d;
            fcv = (d < 10.0f) ? 0.5f * (__cosf(PI * d * 0.1f) + 1.0f) : 0.0f;
            nx = x * inv; ny = y * inv; nz = z * inv;
            f = node_from[e]; to = node_to[e];
        }
        sDist[t] = d;
        sFc[t] = fcv;
        sFcInv[t] = fcv / d;
        sNorm[t][0] = nx; sNorm[t][1] = ny; sNorm[t][2] = nz;
        sFrom[t] = f; sTo[t] = to;
    }
    __syncthreads();
    // rbf fill: 32 edges x 20 freqs
    for (int idx = t; idx < 32 * NRBF; idx += 256) {
        int le = idx & 31;
        int r = idx >> 5;
        sRbf[le][r] = __sinf((float)(r + 1) * PI * sDist[le] * 0.1f) * sFcInv[le];
    }
    __syncthreads();

    const int es = t >> 5;            // edge slot 0..7 (constant within warp)
    const int c0 = (t & 31) * 8;      // col group 0..248

    // bias term (per thread cols, scaled per edge by fc)
    ulonglong2 qb0 = *(const ulonglong2*)(&sWb[c0]);
    ulonglong2 qb1 = *(const ulonglong2*)(&sWb[c0 + 4]);
    u64 wb[4] = {qb0.x, qb0.y, qb1.x, qb1.y};

    u64 acc[4][4];
    #pragma unroll
    for (int m = 0; m < 4; m++) {
        float fc = sFc[es + 8 * m];
        u64 fp = pk2(fc, fc);
        #pragma unroll
        for (int j = 0; j < 4; j++) {
            acc[m][j] = 0ull;
            fma2(acc[m][j], fp, wb[j]);
        }
    }

    // filter GEMM: W_out = rbf_fc @ filt_W + fc*b
    #pragma unroll
    for (int r = 0; r < NRBF; r++) {
        ulonglong2 q0 = *(const ulonglong2*)(&sW[r][c0]);
        ulonglong2 q1 = *(const ulonglong2*)(&sW[r][c0 + 4]);
        u64 b[4] = {q0.x, q0.y, q1.x, q1.y};
        #pragma unroll
        for (int m = 0; m < 4; m++) {
            float a = sRbf[es + 8 * m][r];   // broadcast within warp
            u64 av = pk2(a, a);
            #pragma unroll
            for (int j = 0; j < 4; j++) fma2(acc[m][j], av, b[j]);
        }
    }

    // gather phi, multiply, scatter
    #pragma unroll 1
    for (int m = 0; m < 4; m++) {
        int le = es + 8 * m;
        int e = e0 + le;
        if (e >= NEDGES) continue;
        const float4* ph = (const float4*)(g_phi + (size_t)sFrom[le] * 256 + c0);
        float4 p0 = ph[0];
        float4 p1 = ph[1];
        float2 w0 = upk2(acc[m][0]);
        float2 w1 = upk2(acc[m][1]);
        float2 w2 = upk2(acc[m][2]);
        float2 w3 = upk2(acc[m][3]);
        float pf[8];
        pf[0] = p0.x * w0.x; pf[1] = p0.y * w0.y; pf[2] = p0.z * w1.x; pf[3] = p0.w * w1.y;
        pf[4] = p1.x * w2.x; pf[5] = p1.y * w2.y; pf[6] = p1.z * w3.x; pf[7] = p1.w * w3.y;

        const int to = sTo[le];
        if (c0 < 128) {
            float4* dst = (float4*)(g_state_acc + (size_t)to * D + c0);
            atomicAdd(dst,     make_float4(pf[0], pf[1], pf[2], pf[3]));
            atomicAdd(dst + 1, make_float4(pf[4], pf[5], pf[6], pf[7]));
        } else {
            const int jj = c0 - 128;
            float n0 = sNorm[le][0], n1 = sNorm[le][1], n2 = sNorm[le][2];
            float* base = g_state_vec + (size_t)to * (3 * D) + jj;
            atomicAdd((float4*)(base),             make_float4(n0 * pf[0], n0 * pf[1], n0 * pf[2], n0 * pf[3]));
            atomicAdd((float4*)(base + 4),         make_float4(n0 * pf[4], n0 * pf[5], n0 * pf[6], n0 * pf[7]));
            atomicAdd((float4*)(base + D),         make_float4(n1 * pf[0], n1 * pf[1], n1 * pf[2], n1 * pf[3]));
            atomicAdd((float4*)(base + D + 4),     make_float4(n1 * pf[4], n1 * pf[5], n1 * pf[6], n1 * pf[7]));
            atomicAdd((float4*)(base + 2 * D),     make_float4(n2 * pf[0], n2 * pf[1], n2 * pf[2], n2 * pf[3]));
            atomicAdd((float4*)(base + 2 * D + 4), make_float4(n2 * pf[4], n2 * pf[5], n2 * pf[6], n2 * pf[7]));
        }
    }
}

// ---------------- fused UV kernel: Up/Vp GEMM + UV/Vn reduce ----------------
__global__ __launch_bounds__(256, 2) void uv_kernel(
    const float* __restrict__ U_W, const float* __restrict__ V_W)
{
    __shared__ float sAt[16][132];
    __shared__ float sU[16][132];
    __shared__ float sV[16][132];
    const int t = threadIdx.x;
    const int nb0 = blockIdx.x * 32;
    const int rb = nb0 * 3;
    const int NR = NNODES * 3;

    const int ng = t >> 5;
    const int c0 = (t & 31) * 4;

    u64 acc_u[4][3][2], acc_v[4][3][2];
    #pragma unroll
    for (int m = 0; m < 4; m++)
        #pragma unroll
        for (int c = 0; c < 3; c++)
            #pragma unroll
            for (int j = 0; j < 2; j++) { acc_u[m][c][j] = 0ull; acc_v[m][c][j] = 0ull; }

    for (int k0 = 0; k0 < D; k0 += 16) {
        __syncthreads();
        for (int idx = t; idx < 96 * 16; idx += 256) {
            int row = idx >> 4;
            int k = idx & 15;
            int r = rb + row;
            float v = (r < NR) ? g_state_vec[(size_t)r * D + k0 + k] : 0.f;
            int nl = row / 3, comp = row - nl * 3;
            sAt[k][nl * 4 + comp] = v;
        }
        for (int k = t; k < 16 * 32; k += 256) {
            int row = k >> 5, c4 = k & 31;
            *(float4*)(&sU[row][c4 * 4]) = __ldg((const float4*)(U_W + (k0 + row) * D + c4 * 4));
            *(float4*)(&sV[row][c4 * 4]) = __ldg((const float4*)(V_W + (k0 + row) * D + c4 * 4));
        }
        __syncthreads();
        #pragma unroll
        for (int kk = 0; kk < 16; kk++) {
            ulonglong2 qu = *(const ulonglong2*)(&sU[kk][c0]);
            ulonglong2 qv = *(const ulonglong2*)(&sV[kk][c0]);
            u64 bu[2] = {qu.x, qu.y};
            u64 bv[2] = {qv.x, qv.y};
            #pragma unroll
            for (int m = 0; m < 4; m++) {
                float4 a = *(const float4*)(&sAt[kk][(ng + 8 * m) * 4]);
                u64 d0 = pk2(a.x, a.x), d1 = pk2(a.y, a.y), d2 = pk2(a.z, a.z);
                #pragma unroll
                for (int j = 0; j < 2; j++) {
                    fma2(acc_u[m][0][j], d0, bu[j]);
                    fma2(acc_u[m][1][j], d1, bu[j]);
                    fma2(acc_u[m][2][j], d2, bu[j]);
                    fma2(acc_v[m][0][j], d0, bv[j]);
                    fma2(acc_v[m][1][j], d1, bv[j]);
                    fma2(acc_v[m][2][j], d2, bv[j]);
                }
            }
        }
    }

    #pragma unroll
    for (int m = 0; m < 4; m++) {
        int node = nb0 + ng + 8 * m;
        if (node < NNODES) {
            float uvv[4], vnv[4];
            #pragma unroll
            for (int j = 0; j < 2; j++) {
                float2 U0 = upk2(acc_u[m][0][j]), U1 = upk2(acc_u[m][1][j]), U2 = upk2(acc_u[m][2][j]);
                float2 V0 = upk2(acc_v[m][0][j]), V1 = upk2(acc_v[m][1][j]), V2 = upk2(acc_v[m][2][j]);
                uvv[2 * j]     = U0.x * V0.x + U1.x * V1.x + U2.x * V2.x;
                uvv[2 * j + 1] = U0.y * V0.y + U1.y * V1.y + U2.y * V2.y;
                vnv[2 * j]     = sqrtf(V0.x * V0.x + V1.x * V1.x + V2.x * V2.x);
                vnv[2 * j + 1] = sqrtf(V0.y * V0.y + V1.y * V1.y + V2.y * V2.y);
            }
            *(float4*)(g_UV + (size_t)node * D + c0) = make_float4(uvv[0], uvv[1], uvv[2], uvv[3]);
            *(float4*)(g_Vn + (size_t)node * D + c0) = make_float4(vnv[0], vnv[1], vnv[2], vnv[3]);
        }
    }
}

// ---------------- node update MLP + segment-sum ----------------
__global__ __launch_bounds__(128) void update_kernel(
    const float* __restrict__ upd_W1, const float* __restrict__ upd_b1,
    const float* __restrict__ upd_W2, const float* __restrict__ upd_b2,
    const int* __restrict__ node_graph_index)
{
    __shared__ float sA[32][260];
    __shared__ float sW[32][264];
    const int t = threadIdx.x;
    const int n0 = blockIdx.x * 32;

    for (int k = t; k < 32 * 64; k += 128) {
        int row = k >> 6, c4 = k & 63;
        int n = n0 + row;
        float4 v = make_float4(0.f, 0.f, 0.f, 0.f);
        if (n < NNODES) {
            if (c4 < 32) {
                v = ((const float4*)(g_Vn + (size_t)n * D))[c4];
            } else {
                float4 s0 = ((const float4*)(g_state0 + (size_t)n * D))[c4 - 32];
                float4 s1 = ((const float4*)(g_state_acc + (size_t)n * D))[c4 - 32];
                v = make_float4(s0.x + s1.x, s0.y + s1.y, s0.z + s1.z, s0.w + s1.w);
            }
        }
        *(float4*)(&sA[row][c4 * 4]) = v;
    }

    const int ty = t >> 4;
    const int tx = t & 15;
    const int r0 = ty * 4, c0 = tx * 8;

    u64 acc[4][4];
    #pragma unroll
    for (int i = 0; i < 4; i++)
        #pragma unroll
        for (int j = 0; j < 4; j++) acc[i][j] = 0ull;

    for (int k0 = 0; k0 < 2 * D; k0 += 32) {
        __syncthreads();
        for (int k = t; k < 32 * 32; k += 128) {
            int row = k >> 5, c4 = k & 31;
            *(float4*)(&sW[row][c4 * 4]) = __ldg((const float4*)(upd_W1 + (k0 + row) * D + c4 * 4));
        }
        __syncthreads();
        for (int kk = 0; kk < 32; kk++) {
            u64 ad[4];
            #pragma unroll
            for (int i = 0; i < 4; i++) {
                float a = sA[r0 + i][k0 + kk];
                ad[i] = pk2(a, a);
            }
            ulonglong2 q0 = *(const ulonglong2*)(&sW[kk][c0]);
            ulonglong2 q1 = *(const ulonglong2*)(&sW[kk][c0 + 4]);
            u64 bp[4] = {q0.x, q0.y, q1.x, q1.y};
            #pragma unroll
            for (int i = 0; i < 4; i++)
                #pragma unroll
                for (int j = 0; j < 4; j++) fma2(acc[i][j], ad[i], bp[j]);
        }
    }
    __syncthreads();
    #pragma unroll
    for (int j = 0; j < 4; j++) {
        float bias0 = __ldg(&upd_b1[c0 + 2 * j]);
        float bias1 = __ldg(&upd_b1[c0 + 2 * j + 1]);
        #pragma unroll
        for (int i = 0; i < 4; i++) {
            float2 v = upk2(acc[i][j]);
            sA[r0 + i][c0 + 2 * j] = silu_f(v.x + bias0);
            sA[r0 + i][c0 + 2 * j + 1] = silu_f(v.y + bias1);
        }
    }
    __syncthreads();

    u64 asv[4][4], ass[4][4];
    #pragma unroll
    for (int i = 0; i < 4; i++)
        #pragma unroll
        for (int j = 0; j < 4; j++) { asv[i][j] = 0ull; ass[i][j] = 0ull; }

    for (int k0 = 0; k0 < D; k0 += 32) {
        __syncthreads();
        for (int k = t; k < 32 * 64; k += 128) {
            int row = k >> 6, c4 = k & 63;
            *(float4*)(&sW[row][c4 * 4]) = __ldg((const float4*)(upd_W2 + (k0 + row) * 384 + 128 + c4 * 4));
        }
        __syncthreads();
        for (int kk = 0; kk < 32; kk++) {
            u64 ad[4];
            #pragma unroll
            for (int i = 0; i < 4; i++) {
                float a = sA[r0 + i][k0 + kk];
                ad[i] = pk2(a, a);
            }
            ulonglong2 q0 = *(const ulonglong2*)(&sW[kk][c0]);
            ulonglong2 q1 = *(const ulonglong2*)(&sW[kk][c0 + 4]);
            ulonglong2 q2 = *(const ulonglong2*)(&sW[kk][128 + c0]);
            ulonglong2 q3 = *(const ulonglong2*)(&sW[kk][128 + c0 + 4]);
            u64 bsv[4] = {q0.x, q0.y, q1.x, q1.y};
            u64 bss[4] = {q2.x, q2.y, q3.x, q3.y};
            #pragma unroll
            for (int i = 0; i < 4; i++)
                #pragma unroll
                for (int j = 0; j < 4; j++) {
                    fma2(asv[i][j], ad[i], bsv[j]);
                    fma2(ass[i][j], ad[i], bss[j]);
                }
        }
    }

    int base = __ldg(&node_graph_index[0]);
    #pragma unroll
    for (int i = 0; i < 4; i++) {
        int n = n0 + r0 + i;
        if (n < NNODES) {
            int g = __ldg(&node_graph_index[n]) - base;
            float* dst = g_graph + (size_t)g * D + c0;
            float vals[8];
            #pragma unroll
            for (int j = 0; j < 4; j++) {
                float2 sv = upk2(asv[i][j]);
                float2 ss = upk2(ass[i][j]);
                float uv0 = g_UV[(size_t)n * D + c0 + 2 * j];
                float uv1 = g_UV[(size_t)n * D + c0 + 2 * j + 1];
                float a_sv0 = sv.x + __ldg(&upd_b2[D + c0 + 2 * j]);
                float a_sv1 = sv.y + __ldg(&upd_b2[D + c0 + 2 * j + 1]);
                float a_ss0 = ss.x + __ldg(&upd_b2[2 * D + c0 + 2 * j]);
                float a_ss1 = ss.y + __ldg(&upd_b2[2 * D + c0 + 2 * j + 1]);
                vals[2 * j]     = sA[r0 + i][D + c0 + 2 * j]     + uv0 * a_sv0 + a_ss0;
                vals[2 * j + 1] = sA[r0 + i][D + c0 + 2 * j + 1] + uv1 * a_sv1 + a_ss1;
            }
            atomicAdd((float4*)dst,       make_float4(vals[0], vals[1], vals[2], vals[3]));
            atomicAdd((float4*)(dst + 4), make_float4(vals[4], vals[5], vals[6], vals[7]));
        }
    }
}

// ---------------- output MLP: 512 graphs ----------------
__global__ void out_kernel(
    const float* __restrict__ out_W1, const float* __restrict__ out_b1,
    const float* __restrict__ out_W2, const float* __restrict__ out_b2,
    float* __restrict__ out)
{
    __shared__ float sG[D];
    __shared__ float sRed[D];
    const int g = blockIdx.x;
    const int t = threadIdx.x;
    sG[t] = g_graph[(size_t)g * D + t];
    __syncthreads();
    float x = 0.f;
    #pragma unroll 8
    for (int k = 0; k < D; k++) x += sG[k] * __ldg(&out_W1[k * D + t]);
    x += __ldg(&out_b1[t]);
    float p = silu_f(x) * __ldg(&out_W2[t]);
    sRed[t] = p;
    __syncthreads();
    for (int s = 64; s > 0; s >>= 1) {
        if (t < s) sRed[t] += sRed[t + s];
        __syncthreads();
    }
    if (t == 0) out[g] = sRed[0] + __ldg(&out_b2[0]);
}

// ---------------- launch ----------------
extern "C" void kernel_launch(void* const* d_in, const int* in_sizes, int n_in,
                              void* d_out, int out_size)
{
    const float* edge_vec  = (const float*)d_in[0];
    const float* embedding = (const float*)d_in[1];
    const float* phi_W1 = (const float*)d_in[2];
    const float* phi_b1 = (const float*)d_in[3];
    const float* phi_W2 = (const float*)d_in[4];
    const float* phi_b2 = (const float*)d_in[5];
    const float* filt_W = (const float*)d_in[6];
    const float* filt_b = (const float*)d_in[7];
    const float* upd_W1 = (const float*)d_in[8];
    const float* upd_b1 = (const float*)d_in[9];
    const float* upd_W2 = (const float*)d_in[10];
    const float* upd_b2 = (const float*)d_in[11];
    const float* out_W1 = (const float*)d_in[12];
    const float* out_b1 = (const float*)d_in[13];
    const float* out_W2 = (const float*)d_in[14];
    const float* out_b2 = (const float*)d_in[15];
    const float* U_W    = (const float*)d_in[16];
    const float* V_W    = (const float*)d_in[17];
    const int* atom_types = (const int*)d_in[18];
    const int* node_from  = (const int*)d_in[19];
    const int* node_to    = (const int*)d_in[20];
    const int* node_graph_index = (const int*)d_in[21];
    float* out = (float*)d_out;

    init_kernel<<<2048, 256>>>(embedding, atom_types);
    node_phi_kernel<<<(NNODES + 63) / 64, 128>>>(phi_W1, phi_b1, phi_W2, phi_b2);
    edge_kernel<<<(NEDGES + 31) / 32, 256>>>(edge_vec, filt_W, filt_b, node_from, node_to);
    uv_kernel<<<(NNODES + 31) / 32, 256>>>(U_W, V_W);
    update_kernel<<<(NNODES + 31) / 32, 128>>>(upd_W1, upd_b1, upd_W2, upd_b2, node_graph_index);
    out_kernel<<<NGRAPHS, D>>>(out_W1, out_b1, out_W2, out_b2, out);
}

// round 8
// speedup vs baseline: 1.5600x; 1.0369x over previous
#include <cuda_runtime.h>
#include <math.h>

#define D 128
#define NRBF 20
#define NNODES 25000
#define NEDGES 250000
#define NGRAPHS 512

// ---------------- scratch (device globals; no allocation) ----------------
__device__ float g_state0[NNODES * D];
__device__ float g_state_acc[NNODES * D];
__device__ float g_state_vec[NNODES * 3 * D];
__device__ float g_phi[NNODES * 2 * D];         // per-node phi cols 128..383 (m2|m3)
__device__ float g_UV[NNODES * D];
__device__ float g_Vn[NNODES * D];
__device__ float g_graph[NGRAPHS * D];

typedef unsigned long long u64;

__device__ __forceinline__ float silu_f(float x) {
    return x / (1.0f + __expf(-x));
}

__device__ __forceinline__ u64 pk2(float lo, float hi) {
    u64 r;
    asm("mov.b64 %0, {%1, %2};" : "=l"(r) : "r"(__float_as_uint(lo)), "r"(__float_as_uint(hi)));
    return r;
}
__device__ __forceinline__ float2 upk2(u64 v) {
    unsigned lo, hi;
    asm("mov.b64 {%0, %1}, %2;" : "=r"(lo), "=r"(hi) : "l"(v));
    return make_float2(__uint_as_float(lo), __uint_as_float(hi));
}
__device__ __forceinline__ void fma2(u64& acc, u64 a, u64 b) {
    asm("fma.rn.f32x2 %0, %1, %2, %0;" : "+l"(acc) : "l"(a), "l"(b));
}

// ---------------- init ----------------
__global__ void init_kernel(const float* __restrict__ emb, const int* __restrict__ atype) {
    int stride = gridDim.x * blockDim.x;
    int total = NNODES * 3 * D;
    for (int idx = blockIdx.x * blockDim.x + threadIdx.x; idx < total; idx += stride) {
        g_state_vec[idx] = 0.0f;
        if (idx < NNODES * D) {
            int n = idx >> 7;
            int j = idx & 127;
            g_state0[idx] = emb[atype[n] * D + j];
            g_state_acc[idx] = 0.0f;
        }
        if (idx < NGRAPHS * D) g_graph[idx] = 0.0f;
    }
}

// ---------------- per-node phi MLP ----------------
__global__ __launch_bounds__(128) void node_phi_kernel(
    const float* __restrict__ phi_W1, const float* __restrict__ phi_b1,
    const float* __restrict__ phi_W2, const float* __restrict__ phi_b2)
{
    __shared__ float sA[64][132];
    __shared__ float sW[32][132];
    const int t = threadIdx.x;
    const int n0 = blockIdx.x * 64;

    for (int k = t; k < 64 * 32; k += 128) {
        int row = k >> 5, c4 = k & 31;
        int n = n0 + row;
        float4 v = make_float4(0.f, 0.f, 0.f, 0.f);
        if (n < NNODES) v = ((const float4*)(g_state0 + (size_t)n * D))[c4];
        *(float4*)(&sA[row][c4 * 4]) = v;
    }

    const int ty = t >> 4;
    const int tx = t & 15;
    const int r0 = ty * 8, c0 = tx * 8;

    u64 acc[8][4];
    #pragma unroll
    for (int i = 0; i < 8; i++)
        #pragma unroll
        for (int j = 0; j < 4; j++) acc[i][j] = 0ull;

    for (int k0 = 0; k0 < D; k0 += 32) {
        __syncthreads();
        for (int k = t; k < 32 * 32; k += 128) {
            int row = k >> 5, c4 = k & 31;
            *(float4*)(&sW[row][c4 * 4]) = __ldg((const float4*)(phi_W1 + (k0 + row) * D + c4 * 4));
        }
        __syncthreads();
        for (int kk = 0; kk < 32; kk++) {
            u64 ad[8];
            #pragma unroll
            for (int i = 0; i < 8; i++) {
                float a = sA[r0 + i][k0 + kk];
                ad[i] = pk2(a, a);
            }
            ulonglong2 q0 = *(const ulonglong2*)(&sW[kk][c0]);
            ulonglong2 q1 = *(const ulonglong2*)(&sW[kk][c0 + 4]);
            u64 bp[4] = {q0.x, q0.y, q1.x, q1.y};
            #pragma unroll
            for (int i = 0; i < 8; i++)
                #pragma unroll
                for (int j = 0; j < 4; j++) fma2(acc[i][j], ad[i], bp[j]);
        }
    }
    __syncthreads();
    #pragma unroll
    for (int j = 0; j < 4; j++) {
        float bias0 = __ldg(&phi_b1[c0 + 2 * j]);
        float bias1 = __ldg(&phi_b1[c0 + 2 * j + 1]);
        #pragma unroll
        for (int i = 0; i < 8; i++) {
            float2 v = upk2(acc[i][j]);
            sA[r0 + i][c0 + 2 * j] = silu_f(v.x + bias0);
            sA[r0 + i][c0 + 2 * j + 1] = silu_f(v.y + bias1);
        }
    }
    __syncthreads();

    #pragma unroll 1
    for (int half = 0; half < 2; half++) {
        const int cb = D + half * D;
        u64 acc2[8][4];
        #pragma unroll
        for (int i = 0; i < 8; i++)
            #pragma unroll
            for (int j = 0; j < 4; j++) acc2[i][j] = 0ull;

        for (int k0 = 0; k0 < D; k0 += 32) {
            __syncthreads();
            for (int k = t; k < 32 * 32; k += 128) {
                int row = k >> 5, c4 = k & 31;
                *(float4*)(&sW[row][c4 * 4]) = __ldg((const float4*)(phi_W2 + (k0 + row) * 384 + cb + c4 * 4));
            }
            __syncthreads();
            for (int kk = 0; kk < 32; kk++) {
                u64 ad[8];
                #pragma unroll
                for (int i = 0; i < 8; i++) {
                    float a = sA[r0 + i][k0 + kk];
                    ad[i] = pk2(a, a);
                }
                ulonglong2 q0 = *(const ulonglong2*)(&sW[kk][c0]);
                ulonglong2 q1 = *(const ulonglong2*)(&sW[kk][c0 + 4]);
                u64 bp[4] = {q0.x, q0.y, q1.x, q1.y};
                #pragma unroll
                for (int i = 0; i < 8; i++)
                    #pragma unroll
                    for (int j = 0; j < 4; j++) fma2(acc2[i][j], ad[i], bp[j]);
            }
        }

        #pragma unroll
        for (int i = 0; i < 8; i++) {
            int n = n0 + r0 + i;
            if (n < NNODES) {
                float2 p0 = upk2(acc2[i][0]);
                float2 p1 = upk2(acc2[i][1]);
                float2 p2 = upk2(acc2[i][2]);
                float2 p3 = upk2(acc2[i][3]);
                float4* dst = (float4*)(g_phi + (size_t)n * 256 + half * D + c0);
                dst[0] = make_float4(p0.x + __ldg(&phi_b2[cb + c0 + 0]),
                                     p0.y + __ldg(&phi_b2[cb + c0 + 1]),
                                     p1.x + __ldg(&phi_b2[cb + c0 + 2]),
                                     p1.y + __ldg(&phi_b2[cb + c0 + 3]));
                dst[1] = make_float4(p2.x + __ldg(&phi_b2[cb + c0 + 4]),
                                     p2.y + __ldg(&phi_b2[cb + c0 + 5]),
                                     p3.x + __ldg(&phi_b2[cb + c0 + 6]),
                                     p3.y + __ldg(&phi_b2[cb + c0 + 7]));
            }
        }
    }
}

// ---------------- edge kernel: smem-staged filter GEMM + gather + scatter ----------------
__global__ __launch_bounds__(256) void edge_kernel(
    const float* __restrict__ edge_vec,
    const float* __restrict__ filt_W, const float* __restrict__ filt_b,
    const int* __restrict__ node_from, const int* __restrict__ node_to)
{
    __shared__ float sW[20][264];
    __shared__ float sWb[256];
    __shared__ float sRbf[32][22];
    __shared__ float sFc[32];
    __shared__ float sFcInv[32];
    __shared__ float sDist[32];
    __shared__ float sNorm[32][4];
    __shared__ int   sFrom[32];
    __shared__ int   sTo[32];

    const int t = threadIdx.x;
    const int e0 = blockIdx.x * 32;
    const float PI = 3.14159265358979323846f;

    for (int k = t; k < 20 * 64; k += 256) {
        int row = k >> 6, c4 = k & 63;
        *(float4*)(&sW[row][c4 * 4]) = __ldg((const float4*)(filt_W + row * 384 + 128 + c4 * 4));
    }
    if (t < 64) *(float4*)(&sWb[t * 4]) = __ldg((const float4*)(filt_b + 128 + t * 4));

    if (t < 32) {
        int e = e0 + t;
        float d = 1.f, fcv = 0.f, nx = 0.f, ny = 0.f, nz = 0.f;
        int f = 0, to = 0;
        if (e < NEDGES) {
            float x = edge_vec[3 * e + 0];
            float y = edge_vec[3 * e + 1];
            float z = edge_vec[3 * e + 2];
            d = sqrtf(x * x + y * y + z * z);
            float inv = 1.0f / d;
            fcv = (d < 10.0f) ? 0.5f * (__cosf(PI * d * 0.1f) + 1.0f) : 0.0f;
            nx = x * inv; ny = y * inv; nz = z * inv;
            f = node_from[e]; to = node_to[e];
        }
        sDist[t] = d;
        sFc[t] = fcv;
        sFcInv[t] = fcv / d;
        sNorm[t][0] = nx; sNorm[t][1] = ny; sNorm[t][2] = nz;
        sFrom[t] = f; sTo[t] = to;
    }
    __syncthreads();
    for (int idx = t; idx < 32 * NRBF; idx += 256) {
        int le = idx & 31;
        int r = idx >> 5;
        sRbf[le][r] = __sinf((float)(r + 1) * PI * sDist[le] * 0.1f) * sFcInv[le];
    }
    __syncthreads();

    const int es = t >> 5;
    const int c0 = (t & 31) * 8;

    ulonglong2 qb0 = *(const ulonglong2*)(&sWb[c0]);
    ulonglong2 qb1 = *(const ulonglong2*)(&sWb[c0 + 4]);
    u64 wb[4] = {qb0.x, qb0.y, qb1.x, qb1.y};

    u64 acc[4][4];
    #pragma unroll
    for (int m = 0; m < 4; m++) {
        float fc = sFc[es + 8 * m];
        u64 fp = pk2(fc, fc);
        #pragma unroll
        for (int j = 0; j < 4; j++) {
            acc[m][j] = 0ull;
            fma2(acc[m][j], fp, wb[j]);
        }
    }

    #pragma unroll
    for (int r = 0; r < NRBF; r++) {
        ulonglong2 q0 = *(const ulonglong2*)(&sW[r][c0]);
        ulonglong2 q1 = *(const ulonglong2*)(&sW[r][c0 + 4]);
        u64 b[4] = {q0.x, q0.y, q1.x, q1.y};
        #pragma unroll
        for (int m = 0; m < 4; m++) {
            float a = sRbf[es + 8 * m][r];
            u64 av = pk2(a, a);
            #pragma unroll
            for (int j = 0; j < 4; j++) fma2(acc[m][j], av, b[j]);
        }
    }

    #pragma unroll 1
    for (int m = 0; m < 4; m++) {
        int le = es + 8 * m;
        int e = e0 + le;
        if (e >= NEDGES) continue;
        const float4* ph = (const float4*)(g_phi + (size_t)sFrom[le] * 256 + c0);
        float4 p0 = ph[0];
        float4 p1 = ph[1];
        float2 w0 = upk2(acc[m][0]);
        float2 w1 = upk2(acc[m][1]);
        float2 w2 = upk2(acc[m][2]);
        float2 w3 = upk2(acc[m][3]);
        float pf[8];
        pf[0] = p0.x * w0.x; pf[1] = p0.y * w0.y; pf[2] = p0.z * w1.x; pf[3] = p0.w * w1.y;
        pf[4] = p1.x * w2.x; pf[5] = p1.y * w2.y; pf[6] = p1.z * w3.x; pf[7] = p1.w * w3.y;

        const int to = sTo[le];
        if (c0 < 128) {
            float4* dst = (float4*)(g_state_acc + (size_t)to * D + c0);
            atomicAdd(dst,     make_float4(pf[0], pf[1], pf[2], pf[3]));
            atomicAdd(dst + 1, make_float4(pf[4], pf[5], pf[6], pf[7]));
        } else {
            const int jj = c0 - 128;
            float n0 = sNorm[le][0], n1 = sNorm[le][1], n2 = sNorm[le][2];
            float* base = g_state_vec + (size_t)to * (3 * D) + jj;
            atomicAdd((float4*)(base),             make_float4(n0 * pf[0], n0 * pf[1], n0 * pf[2], n0 * pf[3]));
            atomicAdd((float4*)(base + 4),         make_float4(n0 * pf[4], n0 * pf[5], n0 * pf[6], n0 * pf[7]));
            atomicAdd((float4*)(base + D),         make_float4(n1 * pf[0], n1 * pf[1], n1 * pf[2], n1 * pf[3]));
            atomicAdd((float4*)(base + D + 4),     make_float4(n1 * pf[4], n1 * pf[5], n1 * pf[6], n1 * pf[7]));
            atomicAdd((float4*)(base + 2 * D),     make_float4(n2 * pf[0], n2 * pf[1], n2 * pf[2], n2 * pf[3]));
            atomicAdd((float4*)(base + 2 * D + 4), make_float4(n2 * pf[4], n2 * pf[5], n2 * pf[6], n2 * pf[7]));
        }
    }
}

// ---------------- fused UV kernel: Up/Vp GEMM + UV/Vn reduce ----------------
// 16 nodes / block, 256 threads, 3 blocks/SM (24 warps). Thread: 2 nodes x 3 comps x 4 cols.
// 12 u64 accumulators -> low regs -> high occupancy.
__global__ __launch_bounds__(256, 3) void uv_kernel(
    const float* __restrict__ U_W, const float* __restrict__ V_W)
{
    __shared__ float sAt[16][68];    // [kk][node*4+comp], 16 nodes
    __shared__ float sU[16][132];
    __shared__ float sV[16][132];
    const int t = threadIdx.x;
    const int nb0 = blockIdx.x * 16;
    const int rb = nb0 * 3;
    const int NR = NNODES * 3;

    const int ng = t >> 5;          // node group 0..7: nodes ng, ng+8
    const int c0 = (t & 31) * 4;    // 4-col group

    u64 acc_u[2][3][2], acc_v[2][3][2];
    #pragma unroll
    for (int m = 0; m < 2; m++)
        #pragma unroll
        for (int c = 0; c < 3; c++)
            #pragma unroll
            for (int j = 0; j < 2; j++) { acc_u[m][c][j] = 0ull; acc_v[m][c][j] = 0ull; }

    for (int k0 = 0; k0 < D; k0 += 16) {
        __syncthreads();
        // stage A tile: 48 rows x 16 k, transposed into sAt[k][nl*4+comp]
        for (int idx = t; idx < 48 * 16; idx += 256) {
            int row = idx >> 4;          // 0..47
            int k = idx & 15;
            int r = rb + row;
            float v = (r < NR) ? g_state_vec[(size_t)r * D + k0 + k] : 0.f;
            int nl = row / 3, comp = row - nl * 3;
            sAt[k][nl * 4 + comp] = v;
        }
        // stage U/V tiles: 16 rows x 32 float4
        for (int k = t; k < 16 * 32; k += 256) {
            int row = k >> 5, c4 = k & 31;
            *(float4*)(&sU[row][c4 * 4]) = __ldg((const float4*)(U_W + (k0 + row) * D + c4 * 4));
            *(float4*)(&sV[row][c4 * 4]) = __ldg((const float4*)(V_W + (k0 + row) * D + c4 * 4));
        }
        __syncthreads();
        #pragma unroll
        for (int kk = 0; kk < 16; kk++) {
            ulonglong2 qu = *(const ulonglong2*)(&sU[kk][c0]);
            ulonglong2 qv = *(const ulonglong2*)(&sV[kk][c0]);
            u64 bu[2] = {qu.x, qu.y};
            u64 bv[2] = {qv.x, qv.y};
            #pragma unroll
            for (int m = 0; m < 2; m++) {
                float4 a = *(const float4*)(&sAt[kk][(ng + 8 * m) * 4]);
                u64 d0 = pk2(a.x, a.x), d1 = pk2(a.y, a.y), d2 = pk2(a.z, a.z);
                #pragma unroll
                for (int j = 0; j < 2; j++) {
                    fma2(acc_u[m][0][j], d0, bu[j]);
                    fma2(acc_u[m][1][j], d1, bu[j]);
                    fma2(acc_u[m][2][j], d2, bu[j]);
                    fma2(acc_v[m][0][j], d0, bv[j]);
                    fma2(acc_v[m][1][j], d1, bv[j]);
                    fma2(acc_v[m][2][j], d2, bv[j]);
                }
            }
        }
    }

    #pragma unroll
    for (int m = 0; m < 2; m++) {
        int node = nb0 + ng + 8 * m;
        if (node < NNODES) {
            float uvv[4], vnv[4];
            #pragma unroll
            for (int j = 0; j < 2; j++) {
                float2 U0 = upk2(acc_u[m][0][j]), U1 = upk2(acc_u[m][1][j]), U2 = upk2(acc_u[m][2][j]);
                float2 V0 = upk2(acc_v[m][0][j]), V1 = upk2(acc_v[m][1][j]), V2 = upk2(acc_v[m][2][j]);
                uvv[2 * j]     = U0.x * V0.x + U1.x * V1.x + U2.x * V2.x;
                uvv[2 * j + 1] = U0.y * V0.y + U1.y * V1.y + U2.y * V2.y;
                vnv[2 * j]     = sqrtf(V0.x * V0.x + V1.x * V1.x + V2.x * V2.x);
                vnv[2 * j + 1] = sqrtf(V0.y * V0.y + V1.y * V1.y + V2.y * V2.y);
            }
            *(float4*)(g_UV + (size_t)node * D + c0) = make_float4(uvv[0], uvv[1], uvv[2], uvv[3]);
            *(float4*)(g_Vn + (size_t)node * D + c0) = make_float4(vnv[0], vnv[1], vnv[2], vnv[3]);
        }
    }
}

// ---------------- node update MLP + segment-sum ----------------
__global__ __launch_bounds__(128) void update_kernel(
    const float* __restrict__ upd_W1, const float* __restrict__ upd_b1,
    const float* __restrict__ upd_W2, const float* __restrict__ upd_b2,
    const int* __restrict__ node_graph_index)
{
    __shared__ float sA[32][260];
    __shared__ float sW[32][264];
    const int t = threadIdx.x;
    const int n0 = blockIdx.x * 32;

    for (int k = t; k < 32 * 64; k += 128) {
        int row = k >> 6, c4 = k & 63;
        int n = n0 + row;
        float4 v = make_float4(0.f, 0.f, 0.f, 0.f);
        if (n < NNODES) {
            if (c4 < 32) {
                v = ((const float4*)(g_Vn + (size_t)n * D))[c4];
            } else {
                float4 s0 = ((const float4*)(g_state0 + (size_t)n * D))[c4 - 32];
                float4 s1 = ((const float4*)(g_state_acc + (size_t)n * D))[c4 - 32];
                v = make_float4(s0.x + s1.x, s0.y + s1.y, s0.z + s1.z, s0.w + s1.w);
            }
        }
        *(float4*)(&sA[row][c4 * 4]) = v;
    }

    const int ty = t >> 4;
    const int tx = t & 15;
    const int r0 = ty * 4, c0 = tx * 8;

    u64 acc[4][4];
    #pragma unroll
    for (int i = 0; i < 4; i++)
        #pragma unroll
        for (int j = 0; j < 4; j++) acc[i][j] = 0ull;

    for (int k0 = 0; k0 < 2 * D; k0 += 32) {
        __syncthreads();
        for (int k = t; k < 32 * 32; k += 128) {
            int row = k >> 5, c4 = k & 31;
            *(float4*)(&sW[row][c4 * 4]) = __ldg((const float4*)(upd_W1 + (k0 + row) * D + c4 * 4));
        }
        __syncthreads();
        for (int kk = 0; kk < 32; kk++) {
            u64 ad[4];
            #pragma unroll
            for (int i = 0; i < 4; i++) {
                float a = sA[r0 + i][k0 + kk];
                ad[i] = pk2(a, a);
            }
            ulonglong2 q0 = *(const ulonglong2*)(&sW[kk][c0]);
            ulonglong2 q1 = *(const ulonglong2*)(&sW[kk][c0 + 4]);
            u64 bp[4] = {q0.x, q0.y, q1.x, q1.y};
            #pragma unroll
            for (int i = 0; i < 4; i++)
                #pragma unroll
                for (int j = 0; j < 4; j++) fma2(acc[i][j], ad[i], bp[j]);
        }
    }
    __syncthreads();
    #pragma unroll
    for (int j = 0; j < 4; j++) {
        float bias0 = __ldg(&upd_b1[c0 + 2 * j]);
        float bias1 = __ldg(&upd_b1[c0 + 2 * j + 1]);
        #pragma unroll
        for (int i = 0; i < 4; i++) {
            float2 v = upk2(acc[i][j]);
            sA[r0 + i][c0 + 2 * j] = silu_f(v.x + bias0);
            sA[r0 + i][c0 + 2 * j + 1] = silu_f(v.y + bias1);
        }
    }
    __syncthreads();

    u64 asv[4][4], ass[4][4];
    #pragma unroll
    for (int i = 0; i < 4; i++)
        #pragma unroll
        for (int j = 0; j < 4; j++) { asv[i][j] = 0ull; ass[i][j] = 0ull; }

    for (int k0 = 0; k0 < D; k0 += 32) {
        __syncthreads();
        for (int k = t; k < 32 * 64; k += 128) {
            int row = k >> 6, c4 = k & 63;
            *(float4*)(&sW[row][c4 * 4]) = __ldg((const float4*)(upd_W2 + (k0 + row) * 384 + 128 + c4 * 4));
        }
        __syncthreads();
        for (int kk = 0; kk < 32; kk++) {
            u64 ad[4];
            #pragma unroll
            for (int i = 0; i < 4; i++) {
                float a = sA[r0 + i][k0 + kk];
                ad[i] = pk2(a, a);
            }
            ulonglong2 q0 = *(const ulonglong2*)(&sW[kk][c0]);
            ulonglong2 q1 = *(const ulonglong2*)(&sW[kk][c0 + 4]);
            ulonglong2 q2 = *(const ulonglong2*)(&sW[kk][128 + c0]);
            ulonglong2 q3 = *(const ulonglong2*)(&sW[kk][128 + c0 + 4]);
            u64 bsv[4] = {q0.x, q0.y, q1.x, q1.y};
            u64 bss[4] = {q2.x, q2.y, q3.x, q3.y};
            #pragma unroll
            for (int i = 0; i < 4; i++)
                #pragma unroll
                for (int j = 0; j < 4; j++) {
                    fma2(asv[i][j], ad[i], bsv[j]);
                    fma2(ass[i][j], ad[i], bss[j]);
                }
        }
    }

    int base = __ldg(&node_graph_index[0]);
    #pragma unroll
    for (int i = 0; i < 4; i++) {
        int n = n0 + r0 + i;
        if (n < NNODES) {
            int g = __ldg(&node_graph_index[n]) - base;
            float* dst = g_graph + (size_t)g * D + c0;
            float vals[8];
            #pragma unroll
            for (int j = 0; j < 4; j++) {
                float2 sv = upk2(asv[i][j]);
                float2 ss = upk2(ass[i][j]);
                float uv0 = g_UV[(size_t)n * D + c0 + 2 * j];
                float uv1 = g_UV[(size_t)n * D + c0 + 2 * j + 1];
                float a_sv0 = sv.x + __ldg(&upd_b2[D + c0 + 2 * j]);
                float a_sv1 = sv.y + __ldg(&upd_b2[D + c0 + 2 * j + 1]);
                float a_ss0 = ss.x + __ldg(&upd_b2[2 * D + c0 + 2 * j]);
                float a_ss1 = ss.y + __ldg(&upd_b2[2 * D + c0 + 2 * j + 1]);
                vals[2 * j]     = sA[r0 + i][D + c0 + 2 * j]     + uv0 * a_sv0 + a_ss0;
                vals[2 * j + 1] = sA[r0 + i][D + c0 + 2 * j + 1] + uv1 * a_sv1 + a_ss1;
            }
            atomicAdd((float4*)dst,       make_float4(vals[0], vals[1], vals[2], vals[3]));
            atomicAdd((float4*)(dst + 4), make_float4(vals[4], vals[5], vals[6], vals[7]));
        }
    }
}

// ---------------- output MLP: 512 graphs ----------------
__global__ void out_kernel(
    const float* __restrict__ out_W1, const float* __restrict__ out_b1,
    const float* __restrict__ out_W2, const float* __restrict__ out_b2,
    float* __restrict__ out)
{
    __shared__ float sG[D];
    __shared__ float sRed[D];
    const int g = blockIdx.x;
    const int t = threadIdx.x;
    sG[t] = g_graph[(size_t)g * D + t];
    __syncthreads();
    float x = 0.f;
    #pragma unroll 8
    for (int k = 0; k < D; k++) x += sG[k] * __ldg(&out_W1[k * D + t]);
    x += __ldg(&out_b1[t]);
    float p = silu_f(x) * __ldg(&out_W2[t]);
    sRed[t] = p;
    __syncthreads();
    for (int s = 64; s > 0; s >>= 1) {
        if (t < s) sRed[t] += sRed[t + s];
        __syncthreads();
    }
    if (t == 0) out[g] = sRed[0] + __ldg(&out_b2[0]);
}

// ---------------- launch ----------------
extern "C" void kernel_launch(void* const* d_in, const int* in_sizes, int n_in,
                              void* d_out, int out_size)
{
    const float* edge_vec  = (const float*)d_in[0];
    const float* embedding = (const float*)d_in[1];
    const float* phi_W1 = (const float*)d_in[2];
    const float* phi_b1 = (const float*)d_in[3];
    const float* phi_W2 = (const float*)d_in[4];
    const float* phi_b2 = (const float*)d_in[5];
    const float* filt_W = (const float*)d_in[6];
    const float* filt_b = (const float*)d_in[7];
    const float* upd_W1 = (const float*)d_in[8];
    const float* upd_b1 = (const float*)d_in[9];
    const float* upd_W2 = (const float*)d_in[10];
    const float* upd_b2 = (const float*)d_in[11];
    const float* out_W1 = (const float*)d_in[12];
    const float* out_b1 = (const float*)d_in[13];
    const float* out_W2 = (const float*)d_in[14];
    const float* out_b2 = (const float*)d_in[15];
    const float* U_W    = (const float*)d_in[16];
    const float* V_W    = (const float*)d_in[17];
    const int* atom_types = (const int*)d_in[18];
    const int* node_from  = (const int*)d_in[19];
    const int* node_to    = (const int*)d_in[20];
    const int* node_graph_index = (const int*)d_in[21];
    float* out = (float*)d_out;

    init_kernel<<<2048, 256>>>(embedding, atom_types);
    node_phi_kernel<<<(NNODES + 63) / 64, 128>>>(phi_W1, phi_b1, phi_W2, phi_b2);
    edge_kernel<<<(NEDGES + 31) / 32, 256>>>(edge_vec, filt_W, filt_b, node_from, node_to);
    uv_kernel<<<(NNODES + 15) / 16, 256>>>(U_W, V_W);
    update_kernel<<<(NNODES + 31) / 32, 128>>>(upd_W1, upd_b1, upd_W2, upd_b2, node_graph_index);
    out_kernel<<<NGRAPHS, D>>>(out_W1, out_b1, out_W2, out_b2, out);
}